// round 13
// baseline (speedup 1.0000x reference)
#include <cuda_runtime.h>
#include <cstdint>

#define T_DIM 2048
#define S_DIM 2048
#define B_DIM 2
#define E_DIM 256
#define H_DIM 8
#define DH    32
#define SCLOG2E 0.25503511091247115f   // (1/sqrt(32)) * log2(e)

// Scratch (device globals: no allocation allowed in kernel_launch)
__device__ float    g_qproj[(size_t)T_DIM * B_DIM * E_DIM];
__device__ uint32_t g_khi[(size_t)S_DIM * B_DIM * (E_DIM / 2)];  // packed bf16x2 hi
__device__ uint32_t g_klo[(size_t)S_DIM * B_DIM * (E_DIM / 2)];  // packed bf16x2 lo
__device__ float    g_attnout[(size_t)T_DIM * B_DIM * E_DIM];

// ---------------- conversion helpers ----------------
__device__ __forceinline__ uint32_t f2tf32(float f) {
    uint32_t r; asm("cvt.rna.tf32.f32 %0, %1;" : "=r"(r) : "f"(f)); return r;
}
__device__ __forceinline__ float tf2f(uint32_t u) { return __uint_as_float(u); }
__device__ __forceinline__ float ex2f(float x) {
    float y; asm("ex2.approx.f32 %0, %1;" : "=f"(y) : "f"(x)); return y;
}
__device__ __forceinline__ uint32_t bfpack(float hi, float lo) {
    uint32_t r; asm("cvt.rn.bf16x2.f32 %0, %1, %2;" : "=r"(r) : "f"(hi), "f"(lo)); return r;
}
__device__ __forceinline__ float bflo_f(uint32_t u) { return __uint_as_float(u << 16); }
__device__ __forceinline__ float bfhi_f(uint32_t u) { return __uint_as_float(u & 0xffff0000u); }

__device__ __forceinline__ void mma_tf32(float* d, const uint32_t* a, const uint32_t* b) {
    asm volatile(
        "mma.sync.aligned.m16n8k8.row.col.f32.tf32.tf32.f32 "
        "{%0,%1,%2,%3}, {%4,%5,%6,%7}, {%8,%9}, {%0,%1,%2,%3};"
        : "+f"(d[0]), "+f"(d[1]), "+f"(d[2]), "+f"(d[3])
        : "r"(a[0]), "r"(a[1]), "r"(a[2]), "r"(a[3]), "r"(b[0]), "r"(b[1]));
}
__device__ __forceinline__ void mma_bf16(float* d, const uint32_t* a, const uint32_t* b) {
    asm volatile(
        "mma.sync.aligned.m16n8k16.row.col.f32.bf16.bf16.f32 "
        "{%0,%1,%2,%3}, {%4,%5,%6,%7}, {%8,%9}, {%0,%1,%2,%3};"
        : "+f"(d[0]), "+f"(d[1]), "+f"(d[2]), "+f"(d[3])
        : "r"(a[0]), "r"(a[1]), "r"(a[2]), "r"(a[3]), "r"(b[0]), "r"(b[1]));
}

// ---------------- cp.async helpers ----------------
__device__ __forceinline__ void cpa16(uint32_t s, const void* g) {
    asm volatile("cp.async.ca.shared.global [%0], [%1], 16;" :: "r"(s), "l"(g) : "memory");
}
#define CP_COMMIT() asm volatile("cp.async.commit_group;" ::: "memory")
#define CP_WAIT0()  asm volatile("cp.async.wait_group 0;" ::: "memory")

// attn smem layout (words)
#define KWSTR 132
#define VSTR  264
#define PSTR  36
#define PHEAD (32 * PSTR)
#define PS_SSZ (8 * 32 * PSTR)             //  9216 words per Ps stage
#define KH_OFF 0
#define KL_OFF (2 * 32 * KWSTR)            //  8448
#define V_OFF  (4 * 32 * KWSTR)            // 16896
#define PS_OFF (V_OFF + 2 * 32 * VSTR)     // 33792
#define SMEM_WORDS (PS_OFF + 2 * PS_SSZ)   // 52224 -> 208896 B
#define P1STAGE (128 * KWSTR)              // 16896 (pass1 Kh stages fill [0,PS_OFF))

// proj smem layout (floats): Ws[2][256*36] | Xh[2][32*36] | Xl[2][32*36]
#define PJ_WSZ   (256 * 36)
#define PJ_XSZ   (32 * 36)
#define PJ_XH0   (2 * PJ_WSZ)
#define PJ_XL0   (2 * PJ_WSZ + 2 * PJ_XSZ)
#define PJ_FLOATS (2 * PJ_WSZ + 4 * PJ_XSZ) // 23040 -> 92160 B

// ---------------------------------------------------------------------------
// proj body: 3xTF32, 32 rows x 256 cols per block, W split in-kernel,
// 2-stage cp.async pipeline (R10/R11 version, bit-identical math).
// ---------------------------------------------------------------------------
__device__ __forceinline__ void proj_tc_body(
    const float* __restrict__ X, const float* __restrict__ W,
    const float* __restrict__ bias, float* __restrict__ Y,
    uint32_t* __restrict__ khi, uint32_t* __restrict__ klo,
    int add_residual, int r0)
{
    extern __shared__ float pj[];
    const uint32_t sbase = (uint32_t)__cvta_generic_to_shared(pj);

    const int tid  = threadIdx.x;
    const int w    = tid >> 5;
    const int lane = tid & 31;
    const int g    = lane >> 2;
    const int tig  = lane & 3;

    float d[2][4][4];
#pragma unroll
    for (int mt = 0; mt < 2; mt++)
#pragma unroll
        for (int nt = 0; nt < 4; nt++)
#pragma unroll
            for (int r = 0; r < 4; r++) d[mt][nt][r] = 0.f;

    float xv[4];
#pragma unroll
    for (int i = 0; i < 8; i++) {
        int idx = tid + i * 256;
        int n = idx >> 3, c4 = (idx & 7) * 4;
        cpa16(sbase + (uint32_t)(n * 36 + c4) * 4, &W[(size_t)n * E_DIM + c4]);
    }
    CP_COMMIT();
#pragma unroll
    for (int i = 0; i < 4; i++) {
        int idx = tid + i * 256;
        int r = idx >> 5, e = idx & 31;
        xv[i] = X[(size_t)(r0 + r) * E_DIM + e];
    }

    for (int c = 0; c < 8; c++) {
        const int st = c & 1;
        float* Ws = pj + st * PJ_WSZ;
        float* Xh = pj + PJ_XH0 + st * PJ_XSZ;
        float* Xl = pj + PJ_XL0 + st * PJ_XSZ;

#pragma unroll
        for (int i = 0; i < 4; i++) {
            int idx = tid + i * 256;
            int r = idx >> 5, e = idx & 31;
            float hh = tf2f(f2tf32(xv[i]));
            Xh[r * 36 + e] = hh;
            Xl[r * 36 + e] = xv[i] - hh;
        }
        CP_WAIT0();
        __syncthreads();

        if (c + 1 < 8) {
            int e0n = (c + 1) * 32;
            uint32_t dst = sbase + (uint32_t)((st ^ 1) * PJ_WSZ) * 4;
#pragma unroll
            for (int i = 0; i < 8; i++) {
                int idx = tid + i * 256;
                int n = idx >> 3, c4 = (idx & 7) * 4;
                cpa16(dst + (uint32_t)(n * 36 + c4) * 4, &W[(size_t)n * E_DIM + e0n + c4]);
            }
            CP_COMMIT();
#pragma unroll
            for (int i = 0; i < 4; i++) {
                int idx = tid + i * 256;
                int r = idx >> 5, e = idx & 31;
                xv[i] = X[(size_t)(r0 + r) * E_DIM + e0n + e];
            }
        }

#pragma unroll
        for (int k8 = 0; k8 < 4; k8++) {
            uint32_t ah[2][4], al[2][4];
#pragma unroll
            for (int mt = 0; mt < 2; mt++) {
                int rA = mt * 16 + g;
                ah[mt][0] = __float_as_uint(Xh[rA * 36 + k8 * 8 + tig]);
                ah[mt][1] = __float_as_uint(Xh[(rA + 8) * 36 + k8 * 8 + tig]);
                ah[mt][2] = __float_as_uint(Xh[rA * 36 + k8 * 8 + tig + 4]);
                ah[mt][3] = __float_as_uint(Xh[(rA + 8) * 36 + k8 * 8 + tig + 4]);
                al[mt][0] = f2tf32(Xl[rA * 36 + k8 * 8 + tig]);
                al[mt][1] = f2tf32(Xl[(rA + 8) * 36 + k8 * 8 + tig]);
                al[mt][2] = f2tf32(Xl[rA * 36 + k8 * 8 + tig + 4]);
                al[mt][3] = f2tf32(Xl[(rA + 8) * 36 + k8 * 8 + tig + 4]);
            }
#pragma unroll
            for (int nt = 0; nt < 4; nt++) {
                int n = w * 32 + nt * 8 + g;
                float w0 = Ws[n * 36 + k8 * 8 + tig], w1 = Ws[n * 36 + k8 * 8 + tig + 4];
                uint32_t bh[2], bl[2];
                bh[0] = f2tf32(w0); bl[0] = f2tf32(w0 - tf2f(bh[0]));
                bh[1] = f2tf32(w1); bl[1] = f2tf32(w1 - tf2f(bh[1]));
                mma_tf32(d[0][nt], ah[0], bh);
                mma_tf32(d[1][nt], ah[1], bh);
                mma_tf32(d[0][nt], al[0], bh);
                mma_tf32(d[1][nt], al[1], bh);
                mma_tf32(d[0][nt], ah[0], bl);
                mma_tf32(d[1][nt], ah[1], bl);
            }
        }
    }

#pragma unroll
    for (int mt = 0; mt < 2; mt++) {
#pragma unroll
        for (int nt = 0; nt < 4; nt++) {
            int c = w * 32 + nt * 8 + 2 * tig;
            float b0 = __ldg(&bias[c]), b1 = __ldg(&bias[c + 1]);
            int ra = r0 + mt * 16 + g;
            int rb2 = ra + 8;
            float y0 = d[mt][nt][0] + b0, y1 = d[mt][nt][1] + b1;
            float y2 = d[mt][nt][2] + b0, y3 = d[mt][nt][3] + b1;
            if (khi) {
                uint32_t hi0 = bfpack(y1, y0);
                uint32_t lo0 = bfpack(y1 - bfhi_f(hi0), y0 - bflo_f(hi0));
                uint32_t hi1 = bfpack(y3, y2);
                uint32_t lo1 = bfpack(y3 - bfhi_f(hi1), y2 - bflo_f(hi1));
                khi[(size_t)ra  * 128 + (c >> 1)] = hi0;
                klo[(size_t)ra  * 128 + (c >> 1)] = lo0;
                khi[(size_t)rb2 * 128 + (c >> 1)] = hi1;
                klo[(size_t)rb2 * 128 + (c >> 1)] = lo1;
            } else {
                size_t o0 = (size_t)ra  * E_DIM + c;
                size_t o1 = (size_t)rb2 * E_DIM + c;
                if (add_residual) {
                    float2 x0 = *(const float2*)&X[o0];
                    float2 x1 = *(const float2*)&X[o1];
                    y0 += x0.x; y1 += x0.y; y2 += x1.x; y3 += x1.y;
                }
                *(float2*)&Y[o0] = make_float2(y0, y1);
                *(float2*)&Y[o1] = make_float2(y2, y3);
            }
        }
    }
}

__global__ __launch_bounds__(256, 2) void proj_qk_kernel(
    const float* __restrict__ Xq, const float* __restrict__ Wq, const float* __restrict__ bq,
    const float* __restrict__ Xk, const float* __restrict__ Wk, const float* __restrict__ bk,
    float* __restrict__ Yq, uint32_t* __restrict__ khi, uint32_t* __restrict__ klo)
{
    int r0 = blockIdx.x * 32;
    if (blockIdx.y == 0) proj_tc_body(Xq, Wq, bq, Yq, nullptr, nullptr, 0, r0);
    else                 proj_tc_body(Xk, Wk, bk, nullptr, khi, klo, 0, r0);
}

__global__ __launch_bounds__(256, 2) void proj_o_kernel(
    const float* __restrict__ X, const float* __restrict__ W,
    const float* __restrict__ bias, float* __restrict__ Y)
{
    proj_tc_body(X, W, bias, Y, nullptr, nullptr, 1, blockIdx.x * 32);
}

// ---------------------------------------------------------------------------
// attn_tc_kernel: 512 threads, 2-stage cp.async.
// Pass1: 1-term bf16 QK on 128-row s-tiles.
// Pass2: 2-split bf16 QK + 1xTF32 PV on 32-row s-tiles; Ps double-buffered,
// avgw reduction for tile t deferred to iteration t+1 -> ONE barrier/tile.
// ---------------------------------------------------------------------------
__global__ __launch_bounds__(512, 1) void attn_tc_kernel(
    const float* __restrict__ value,
    float* __restrict__ avgw,
    float* __restrict__ attn_out)
{
    extern __shared__ uint32_t smu[];
    float* Psb = (float*)(smu + PS_OFF);   // two stages of 8*32*PSTR
    __shared__ float Lsh[16][32][4];

    const uint32_t sb = (uint32_t)__cvta_generic_to_shared(smu);

    const int tid  = threadIdx.x;
    const int wid  = tid >> 5;
    const int h    = wid & 7;
    const int sh   = wid >> 3;
    const int lane = tid & 31;
    const int g    = lane >> 2;
    const int tig  = lane & 3;
    const int t0   = blockIdx.x * 32;
    const int b    = blockIdx.y;
    const int hb   = h * DH;
    const int hw   = hb >> 1;

    // ---- Q fragments: bf16 2-split ----
    uint32_t qh[2][2][4], ql[2][2][4];
#pragma unroll
    for (int mt = 0; mt < 2; mt++) {
#pragma unroll
        for (int jc = 0; jc < 2; jc++) {
            int r = t0 + mt * 16 + g;
            int c = hb + jc * 16 + 2 * tig;
            float2 v0 = *(const float2*)&g_qproj[((size_t)r       * B_DIM + b) * E_DIM + c];
            float2 v1 = *(const float2*)&g_qproj[((size_t)(r + 8) * B_DIM + b) * E_DIM + c];
            float2 v2 = *(const float2*)&g_qproj[((size_t)r       * B_DIM + b) * E_DIM + c + 8];
            float2 v3 = *(const float2*)&g_qproj[((size_t)(r + 8) * B_DIM + b) * E_DIM + c + 8];
            qh[mt][jc][0] = bfpack(v0.y, v0.x);
            qh[mt][jc][1] = bfpack(v1.y, v1.x);
            qh[mt][jc][2] = bfpack(v2.y, v2.x);
            qh[mt][jc][3] = bfpack(v3.y, v3.x);
            ql[mt][jc][0] = bfpack(v0.y - bfhi_f(qh[mt][jc][0]), v0.x - bflo_f(qh[mt][jc][0]));
            ql[mt][jc][1] = bfpack(v1.y - bfhi_f(qh[mt][jc][1]), v1.x - bflo_f(qh[mt][jc][1]));
            ql[mt][jc][2] = bfpack(v2.y - bfhi_f(qh[mt][jc][2]), v2.x - bflo_f(qh[mt][jc][2]));
            ql[mt][jc][3] = bfpack(v3.y - bfhi_f(qh[mt][jc][3]), v3.x - bflo_f(qh[mt][jc][3]));
        }
    }

    // ========= pass 1: lsum via 1-term bf16 QK, 128-row tiles =========
    float lsum[4] = {0.f, 0.f, 0.f, 0.f};
    {
        const int NT1 = S_DIM / 128;

#pragma unroll
        for (int i = 0; i < 8; i++) {
            int idx = tid + i * 512;
            int row = idx >> 5, c = idx & 31;
            cpa16(sb + (uint32_t)(row * KWSTR + c * 4) * 4,
                  &g_khi[((size_t)row * B_DIM + b) * 128 + c * 4]);
        }
        CP_COMMIT();

        for (int t = 0; t < NT1; t++) {
            CP_WAIT0();
            __syncthreads();
            if (t + 1 < NT1) {
                int s0n = (t + 1) * 128;
                uint32_t dst = sb + (uint32_t)(((t + 1) & 1) * P1STAGE) * 4;
#pragma unroll
                for (int i = 0; i < 8; i++) {
                    int idx = tid + i * 512;
                    int row = idx >> 5, c = idx & 31;
                    cpa16(dst + (uint32_t)(row * KWSTR + c * 4) * 4,
                          &g_khi[((size_t)(s0n + row) * B_DIM + b) * 128 + c * 4]);
                }
            }
            CP_COMMIT();

            const uint32_t* Kh = smu + (t & 1) * P1STAGE;

#pragma unroll
            for (int sub = 0; sub < 2; sub++) {
                const int soW1 = sub * 64 + sh * 32;
                float d[2][4][4];
#pragma unroll
                for (int mt = 0; mt < 2; mt++)
#pragma unroll
                    for (int nt = 0; nt < 4; nt++)
#pragma unroll
                        for (int r = 0; r < 4; r++) d[mt][nt][r] = 0.f;

#pragma unroll
                for (int jc = 0; jc < 2; jc++) {
                    uint32_t bh[4][2];
#pragma unroll
                    for (int nt = 0; nt < 4; nt++) {
                        int base = (soW1 + nt * 8 + g) * KWSTR + hw + jc * 8 + tig;
                        bh[nt][0] = Kh[base]; bh[nt][1] = Kh[base + 4];
                    }
#pragma unroll
                    for (int nt = 0; nt < 4; nt++) {
                        mma_bf16(d[0][nt], qh[0][jc], bh[nt]);
                        mma_bf16(d[1][nt], qh[1][jc], bh[nt]);
                    }
                }
#pragma unroll
                for (int mt = 0; mt < 2; mt++)
#pragma unroll
                    for (int nt = 0; nt < 4; nt++)
#pragma unroll
                        for (int r = 0; r < 4; r++)
                            lsum[mt * 2 + (r >> 1)] += ex2f(d[mt][nt][r] * SCLOG2E);
            }
        }
    }
#pragma unroll
    for (int r = 0; r < 4; r++) {
        lsum[r] += __shfl_xor_sync(0xffffffffu, lsum[r], 1);
        lsum[r] += __shfl_xor_sync(0xffffffffu, lsum[r], 2);
    }
#pragma unroll
    for (int r = 0; r < 4; r++) Lsh[wid][lane][r] = lsum[r];
    __syncthreads();
    float inv[4];
#pragma unroll
    for (int r = 0; r < 4; r++) inv[r] = 1.0f / (lsum[r] + Lsh[wid ^ 8][lane][r]);

    // ================= pass 2 =================
    float o[2][4][4];
#pragma unroll
    for (int mt = 0; mt < 2; mt++)
#pragma unroll
        for (int nd = 0; nd < 4; nd++)
#pragma unroll
            for (int r = 0; r < 4; r++) o[mt][nd][r] = 0.f;

    const int soW = sh * 16;
    const int NT = S_DIM / 32;

    {
        uint32_t dkh = sb + (uint32_t)(KH_OFF) * 4;
        uint32_t dkl = sb + (uint32_t)(KL_OFF) * 4;
        uint32_t dv  = sb + (uint32_t)(V_OFF) * 4;
#pragma unroll
        for (int i = 0; i < 2; i++) {
            int idx = tid + i * 512;
            int row = idx >> 5, c = idx & 31;
            size_t gsrc = ((size_t)row * B_DIM + b) * 128 + c * 4;
            cpa16(dkh + (uint32_t)(row * KWSTR + c * 4) * 4, &g_khi[gsrc]);
            cpa16(dkl + (uint32_t)(row * KWSTR + c * 4) * 4, &g_klo[gsrc]);
        }
#pragma unroll
        for (int i = 0; i < 4; i++) {
            int idx = tid + i * 512;
            int row = idx >> 6, c = idx & 63;
            cpa16(dv + (uint32_t)(row * VSTR + c * 4) * 4,
                  &value[((size_t)row * B_DIM + b) * 256 + c * 4]);
        }
    }
    CP_COMMIT();

    for (int t = 0; t < NT; t++) {
        CP_WAIT0();
        __syncthreads();   // tile t data ready; tile t-1 Ps stores visible
        if (t + 1 < NT) {
            int nst = (t + 1) & 1;
            int s0n = (t + 1) * 32;
            uint32_t dkh = sb + (uint32_t)(KH_OFF + nst * 32 * KWSTR) * 4;
            uint32_t dkl = sb + (uint32_t)(KL_OFF + nst * 32 * KWSTR) * 4;
            uint32_t dv  = sb + (uint32_t)(V_OFF  + nst * 32 * VSTR) * 4;
#pragma unroll
            for (int i = 0; i < 2; i++) {
                int idx = tid + i * 512;
                int row = idx >> 5, c = idx & 31;
                size_t gsrc = ((size_t)(s0n + row) * B_DIM + b) * 128 + c * 4;
                cpa16(dkh + (uint32_t)(row * KWSTR + c * 4) * 4, &g_khi[gsrc]);
                cpa16(dkl + (uint32_t)(row * KWSTR + c * 4) * 4, &g_klo[gsrc]);
            }
#pragma unroll
            for (int i = 0; i < 4; i++) {
                int idx = tid + i * 512;
                int row = idx >> 6, c = idx & 63;
                cpa16(dv + (uint32_t)(row * VSTR + c * 4) * 4,
                      &value[((size_t)(s0n + row) * B_DIM + b) * 256 + c * 4]);
            }
        }
        CP_COMMIT();

        const int st = t & 1;
        const uint32_t* Kh = smu + KH_OFF + st * 32 * KWSTR;
        const uint32_t* Kl = smu + KL_OFF + st * 32 * KWSTR;
        const float*    Vs = (const float*)(smu + V_OFF + st * 32 * VSTR);
        float* Ps = Psb + st * PS_SSZ;

        float d[2][2][4];
#pragma unroll
        for (int mt = 0; mt < 2; mt++)
#pragma unroll
            for (int nt = 0; nt < 2; nt++)
#pragma unroll
                for (int r = 0; r < 4; r++) d[mt][nt][r] = 0.f;

#pragma unroll
        for (int jc = 0; jc < 2; jc++) {
            uint32_t bh[2][2], bl[2][2];
#pragma unroll
            for (int nt = 0; nt < 2; nt++) {
                int base = (soW + nt * 8 + g) * KWSTR + hw + jc * 8 + tig;
                bh[nt][0] = Kh[base]; bh[nt][1] = Kh[base + 4];
                bl[nt][0] = Kl[base]; bl[nt][1] = Kl[base + 4];
            }
#pragma unroll
            for (int nt = 0; nt < 2; nt++) {
                mma_bf16(d[0][nt], qh[0][jc], bh[nt]);
                mma_bf16(d[1][nt], qh[1][jc], bh[nt]);
            }
#pragma unroll
            for (int nt = 0; nt < 2; nt++) {
                mma_bf16(d[0][nt], ql[0][jc], bh[nt]);
                mma_bf16(d[1][nt], ql[1][jc], bh[nt]);
            }
#pragma unroll
            for (int nt = 0; nt < 2; nt++) {
                mma_bf16(d[0][nt], qh[0][jc], bl[nt]);
                mma_bf16(d[1][nt], qh[1][jc], bl[nt]);
            }
        }

        // normalize, stage p into Ps[st]
#pragma unroll
        for (int mt = 0; mt < 2; mt++) {
#pragma unroll
            for (int nt = 0; nt < 2; nt++) {
                float p0 = ex2f(d[mt][nt][0] * SCLOG2E) * inv[mt * 2 + 0];
                float p1 = ex2f(d[mt][nt][1] * SCLOG2E) * inv[mt * 2 + 0];
                float p2 = ex2f(d[mt][nt][2] * SCLOG2E) * inv[mt * 2 + 1];
                float p3 = ex2f(d[mt][nt][3] * SCLOG2E) * inv[mt * 2 + 1];
                int scol = soW + nt * 8 + 2 * tig;
                *(float2*)&Ps[h * PHEAD + (mt * 16 + g)     * PSTR + scol] = make_float2(p0, p1);
                *(float2*)&Ps[h * PHEAD + (mt * 16 + g + 8) * PSTR + scol] = make_float2(p2, p3);
            }
        }
        __syncwarp();

        // PV over this warp's 16 s-rows: 1xTF32 (reads only own Ps columns)
#pragma unroll
        for (int ks = 0; ks < 2; ks++) {
            uint32_t a[2][4];
            int sc = soW + ks * 8 + tig;
#pragma unroll
            for (int mt = 0; mt < 2; mt++) {
                int rb = mt * 16;
                a[mt][0] = f2tf32(Ps[h * PHEAD + (rb + g)     * PSTR + sc]);
                a[mt][1] = f2tf32(Ps[h * PHEAD + (rb + g + 8) * PSTR + sc]);
                a[mt][2] = f2tf32(Ps[h * PHEAD + (rb + g)     * PSTR + sc + 4]);
                a[mt][3] = f2tf32(Ps[h * PHEAD + (rb + g + 8) * PSTR + sc + 4]);
            }
#pragma unroll
            for (int nd = 0; nd < 4; nd++) {
                uint32_t bb[2];
                bb[0] = f2tf32(Vs[(soW + ks * 8 + tig)     * VSTR + hb + nd * 8 + g]);
                bb[1] = f2tf32(Vs[(soW + ks * 8 + tig + 4) * VSTR + hb + nd * 8 + g]);
                mma_tf32(o[0][nd], a[0], bb);
                mma_tf32(o[1][nd], a[1], bb);
            }
        }

        // deferred avg_weights for tile t-1 (its Ps stage is the other one;
        // stores were ordered by this iteration's start barrier)
        if (t > 0) {
            const float* Pp = Psb + ((t - 1) & 1) * PS_SSZ;
            int row = tid >> 4;
            int sb2 = (tid & 15) * 2;
            float2 acc = make_float2(0.f, 0.f);
#pragma unroll
            for (int hh = 0; hh < 8; hh++) {
                float2 x = *(const float2*)&Pp[hh * PHEAD + row * PSTR + sb2];
                acc.x += x.x; acc.y += x.y;
            }
            acc.x *= 0.125f; acc.y *= 0.125f;
            size_t oo = (size_t)b * T_DIM * S_DIM + (size_t)(t0 + row) * S_DIM
                      + (size_t)(t - 1) * 32 + sb2;
            *(float2*)&avgw[oo] = acc;
        }
    }

    // final tile's avg_weights
    __syncthreads();
    {
        const float* Pp = Psb + ((NT - 1) & 1) * PS_SSZ;
        int row = tid >> 4;
        int sb2 = (tid & 15) * 2;
        float2 acc = make_float2(0.f, 0.f);
#pragma unroll
        for (int hh = 0; hh < 8; hh++) {
            float2 x = *(const float2*)&Pp[hh * PHEAD + row * PSTR + sb2];
            acc.x += x.x; acc.y += x.y;
        }
        acc.x *= 0.125f; acc.y *= 0.125f;
        size_t oo = (size_t)b * T_DIM * S_DIM + (size_t)(t0 + row) * S_DIM
                  + (size_t)(NT - 1) * 32 + sb2;
        *(float2*)&avgw[oo] = acc;
    }

    // ---- merge s-half partial PV accumulators, write attn_out ----
    // (reuse the OTHER Ps stage region: last avgw read the (NT-1)&1 stage)
    float* Os = Psb + ((NT) & 1) * PS_SSZ;   // NT=64 -> stage 0
    if (sh == 1) {
#pragma unroll
        for (int mt = 0; mt < 2; mt++)
#pragma unroll
            for (int nd = 0; nd < 4; nd++)
#pragma unroll
                for (int r = 0; r < 4; r++)
                    Os[(h * 32 + lane) * 33 + mt * 16 + nd * 4 + r] = o[mt][nd][r];
    }
    __syncthreads();
    if (sh == 0) {
#pragma unroll
        for (int mt = 0; mt < 2; mt++) {
#pragma unroll
            for (int nd = 0; nd < 4; nd++) {
#pragma unroll
                for (int r = 0; r < 4; r++)
                    o[mt][nd][r] += Os[(h * 32 + lane) * 33 + mt * 16 + nd * 4 + r];
                int col = hb + nd * 8 + 2 * tig;
                size_t b0 = ((size_t)(t0 + mt * 16 + g)     * B_DIM + b) * E_DIM + col;
                size_t b1 = ((size_t)(t0 + mt * 16 + g + 8) * B_DIM + b) * E_DIM + col;
                *(float2*)&attn_out[b0] = make_float2(o[mt][nd][0], o[mt][nd][1]);
                *(float2*)&attn_out[b1] = make_float2(o[mt][nd][2], o[mt][nd][3]);
            }
        }
    }
}

// ---------------------------------------------------------------------------
extern "C" void kernel_launch(void* const* d_in, const int* in_sizes, int n_in,
                              void* d_out, int out_size)
{
    (void)in_sizes; (void)n_in; (void)out_size;

    const float* query = (const float*)d_in[0];
    const float* key   = (const float*)d_in[1];
    const float* value = (const float*)d_in[2];
    const float* Wq    = (const float*)d_in[3];
    const float* bq    = (const float*)d_in[4];
    const float* Wk    = (const float*)d_in[5];
    const float* bk    = (const float*)d_in[6];
    const float* Wo    = (const float*)d_in[7];
    const float* bo    = (const float*)d_in[8];

    float* out  = (float*)d_out;
    float* avgw = out + (size_t)T_DIM * B_DIM * E_DIM;

    float *qp = nullptr, *ao = nullptr;
    uint32_t *khi = nullptr, *klo = nullptr;
    cudaGetSymbolAddress((void**)&qp,  g_qproj);
    cudaGetSymbolAddress((void**)&khi, g_khi);
    cudaGetSymbolAddress((void**)&klo, g_klo);
    cudaGetSymbolAddress((void**)&ao,  g_attnout);

    const int rows_blocks = (T_DIM * B_DIM) / 32;   // 128
    const int pj_smem = PJ_FLOATS * 4;              // 92160

    cudaFuncSetAttribute(proj_qk_kernel, cudaFuncAttributeMaxDynamicSharedMemorySize, pj_smem);
    cudaFuncSetAttribute(proj_o_kernel,  cudaFuncAttributeMaxDynamicSharedMemorySize, pj_smem);

    proj_qk_kernel<<<dim3(rows_blocks, 2), 256, pj_smem>>>(query, Wq, bq, key, Wk, bk, qp, khi, klo);

    const int smem_bytes = SMEM_WORDS * 4;  // 208896
    cudaFuncSetAttribute(attn_tc_kernel, cudaFuncAttributeMaxDynamicSharedMemorySize, smem_bytes);
    attn_tc_kernel<<<dim3(T_DIM / 32, B_DIM), 512, smem_bytes>>>(value, avgw, ao);

    proj_o_kernel<<<rows_blocks, 256, pj_smem>>>(ao, Wo, bo, out);
}

// round 14
// speedup vs baseline: 1.0122x; 1.0122x over previous
#include <cuda_runtime.h>
#include <cstdint>

#define T_DIM 2048
#define S_DIM 2048
#define B_DIM 2
#define E_DIM 256
#define H_DIM 8
#define DH    32
#define SCLOG2E 0.25503511091247115f   // (1/sqrt(32)) * log2(e)

// Scratch (device globals: no allocation allowed in kernel_launch)
__device__ float    g_qproj[(size_t)T_DIM * B_DIM * E_DIM];
__device__ uint32_t g_khi[(size_t)S_DIM * B_DIM * (E_DIM / 2)];  // packed bf16x2 hi
__device__ uint32_t g_klo[(size_t)S_DIM * B_DIM * (E_DIM / 2)];  // packed bf16x2 lo
__device__ float    g_attnout[(size_t)T_DIM * B_DIM * E_DIM];

// ---------------- conversion helpers ----------------
__device__ __forceinline__ uint32_t f2tf32(float f) {
    uint32_t r; asm("cvt.rna.tf32.f32 %0, %1;" : "=r"(r) : "f"(f)); return r;
}
__device__ __forceinline__ float tf2f(uint32_t u) { return __uint_as_float(u); }
__device__ __forceinline__ float ex2f(float x) {
    float y; asm("ex2.approx.f32 %0, %1;" : "=f"(y) : "f"(x)); return y;
}
__device__ __forceinline__ uint32_t bfpack(float hi, float lo) {
    uint32_t r; asm("cvt.rn.bf16x2.f32 %0, %1, %2;" : "=r"(r) : "f"(hi), "f"(lo)); return r;
}
__device__ __forceinline__ float bflo_f(uint32_t u) { return __uint_as_float(u << 16); }
__device__ __forceinline__ float bfhi_f(uint32_t u) { return __uint_as_float(u & 0xffff0000u); }

__device__ __forceinline__ void mma_tf32(float* d, const uint32_t* a, const uint32_t* b) {
    asm volatile(
        "mma.sync.aligned.m16n8k8.row.col.f32.tf32.tf32.f32 "
        "{%0,%1,%2,%3}, {%4,%5,%6,%7}, {%8,%9}, {%0,%1,%2,%3};"
        : "+f"(d[0]), "+f"(d[1]), "+f"(d[2]), "+f"(d[3])
        : "r"(a[0]), "r"(a[1]), "r"(a[2]), "r"(a[3]), "r"(b[0]), "r"(b[1]));
}
__device__ __forceinline__ void mma_bf16(float* d, const uint32_t* a, const uint32_t* b) {
    asm volatile(
        "mma.sync.aligned.m16n8k16.row.col.f32.bf16.bf16.f32 "
        "{%0,%1,%2,%3}, {%4,%5,%6,%7}, {%8,%9}, {%0,%1,%2,%3};"
        : "+f"(d[0]), "+f"(d[1]), "+f"(d[2]), "+f"(d[3])
        : "r"(a[0]), "r"(a[1]), "r"(a[2]), "r"(a[3]), "r"(b[0]), "r"(b[1]));
}

// ---------------- cp.async helpers (.cg: bypass L1, stream via L2) ----------------
__device__ __forceinline__ void cpa16(uint32_t s, const void* g) {
    asm volatile("cp.async.cg.shared.global [%0], [%1], 16;" :: "r"(s), "l"(g) : "memory");
}
#define CP_COMMIT() asm volatile("cp.async.commit_group;" ::: "memory")
#define CP_WAIT0()  asm volatile("cp.async.wait_group 0;" ::: "memory")

// attn smem layout (words)
#define KWSTR 132
#define VSTR  264
#define PSTR  36
#define PHEAD (32 * PSTR)
#define KH_OFF 0
#define KL_OFF (2 * 32 * KWSTR)            //  8448
#define V_OFF  (4 * 32 * KWSTR)            // 16896
#define PS_OFF (V_OFF + 2 * 32 * VSTR)     // 33792
#define SMEM_WORDS (PS_OFF + 8 * 32 * PSTR) // 43008 -> 172032 B
#define P1STAGE (128 * KWSTR)              // 16896 (pass1 Kh stages fill [0,PS_OFF))

// proj smem layout (floats): Ws[2][256*36] | Xh[2][32*36] | Xl[2][32*36]
#define PJ_WSZ   (256 * 36)
#define PJ_XSZ   (32 * 36)
#define PJ_XH0   (2 * PJ_WSZ)
#define PJ_XL0   (2 * PJ_WSZ + 2 * PJ_XSZ)
#define PJ_FLOATS (2 * PJ_WSZ + 4 * PJ_XSZ) // 23040 -> 92160 B

// ---------------------------------------------------------------------------
// proj body: 3xTF32, 32 rows x 256 cols per block, W split in-kernel,
// 2-stage cp.async pipeline (R11 version, bit-identical math).
// ---------------------------------------------------------------------------
__device__ __forceinline__ void proj_tc_body(
    const float* __restrict__ X, const float* __restrict__ W,
    const float* __restrict__ bias, float* __restrict__ Y,
    uint32_t* __restrict__ khi, uint32_t* __restrict__ klo,
    int add_residual, int r0)
{
    extern __shared__ float pj[];
    const uint32_t sbase = (uint32_t)__cvta_generic_to_shared(pj);

    const int tid  = threadIdx.x;
    const int w    = tid >> 5;
    const int lane = tid & 31;
    const int g    = lane >> 2;
    const int tig  = lane & 3;

    float d[2][4][4];
#pragma unroll
    for (int mt = 0; mt < 2; mt++)
#pragma unroll
        for (int nt = 0; nt < 4; nt++)
#pragma unroll
            for (int r = 0; r < 4; r++) d[mt][nt][r] = 0.f;

    float xv[4];
#pragma unroll
    for (int i = 0; i < 8; i++) {
        int idx = tid + i * 256;
        int n = idx >> 3, c4 = (idx & 7) * 4;
        cpa16(sbase + (uint32_t)(n * 36 + c4) * 4, &W[(size_t)n * E_DIM + c4]);
    }
    CP_COMMIT();
#pragma unroll
    for (int i = 0; i < 4; i++) {
        int idx = tid + i * 256;
        int r = idx >> 5, e = idx & 31;
        xv[i] = X[(size_t)(r0 + r) * E_DIM + e];
    }

    for (int c = 0; c < 8; c++) {
        const int st = c & 1;
        float* Ws = pj + st * PJ_WSZ;
        float* Xh = pj + PJ_XH0 + st * PJ_XSZ;
        float* Xl = pj + PJ_XL0 + st * PJ_XSZ;

#pragma unroll
        for (int i = 0; i < 4; i++) {
            int idx = tid + i * 256;
            int r = idx >> 5, e = idx & 31;
            float hh = tf2f(f2tf32(xv[i]));
            Xh[r * 36 + e] = hh;
            Xl[r * 36 + e] = xv[i] - hh;
        }
        CP_WAIT0();
        __syncthreads();

        if (c + 1 < 8) {
            int e0n = (c + 1) * 32;
            uint32_t dst = sbase + (uint32_t)((st ^ 1) * PJ_WSZ) * 4;
#pragma unroll
            for (int i = 0; i < 8; i++) {
                int idx = tid + i * 256;
                int n = idx >> 3, c4 = (idx & 7) * 4;
                cpa16(dst + (uint32_t)(n * 36 + c4) * 4, &W[(size_t)n * E_DIM + e0n + c4]);
            }
            CP_COMMIT();
#pragma unroll
            for (int i = 0; i < 4; i++) {
                int idx = tid + i * 256;
                int r = idx >> 5, e = idx & 31;
                xv[i] = X[(size_t)(r0 + r) * E_DIM + e0n + e];
            }
        }

#pragma unroll
        for (int k8 = 0; k8 < 4; k8++) {
            uint32_t ah[2][4], al[2][4];
#pragma unroll
            for (int mt = 0; mt < 2; mt++) {
                int rA = mt * 16 + g;
                ah[mt][0] = __float_as_uint(Xh[rA * 36 + k8 * 8 + tig]);
                ah[mt][1] = __float_as_uint(Xh[(rA + 8) * 36 + k8 * 8 + tig]);
                ah[mt][2] = __float_as_uint(Xh[rA * 36 + k8 * 8 + tig + 4]);
                ah[mt][3] = __float_as_uint(Xh[(rA + 8) * 36 + k8 * 8 + tig + 4]);
                al[mt][0] = f2tf32(Xl[rA * 36 + k8 * 8 + tig]);
                al[mt][1] = f2tf32(Xl[(rA + 8) * 36 + k8 * 8 + tig]);
                al[mt][2] = f2tf32(Xl[rA * 36 + k8 * 8 + tig + 4]);
                al[mt][3] = f2tf32(Xl[(rA + 8) * 36 + k8 * 8 + tig + 4]);
            }
#pragma unroll
            for (int nt = 0; nt < 4; nt++) {
                int n = w * 32 + nt * 8 + g;
                float w0 = Ws[n * 36 + k8 * 8 + tig], w1 = Ws[n * 36 + k8 * 8 + tig + 4];
                uint32_t bh[2], bl[2];
                bh[0] = f2tf32(w0); bl[0] = f2tf32(w0 - tf2f(bh[0]));
                bh[1] = f2tf32(w1); bl[1] = f2tf32(w1 - tf2f(bh[1]));
                mma_tf32(d[0][nt], ah[0], bh);
                mma_tf32(d[1][nt], ah[1], bh);
                mma_tf32(d[0][nt], al[0], bh);
                mma_tf32(d[1][nt], al[1], bh);
                mma_tf32(d[0][nt], ah[0], bl);
                mma_tf32(d[1][nt], ah[1], bl);
            }
        }
    }

#pragma unroll
    for (int mt = 0; mt < 2; mt++) {
#pragma unroll
        for (int nt = 0; nt < 4; nt++) {
            int c = w * 32 + nt * 8 + 2 * tig;
            float b0 = __ldg(&bias[c]), b1 = __ldg(&bias[c + 1]);
            int ra = r0 + mt * 16 + g;
            int rb2 = ra + 8;
            float y0 = d[mt][nt][0] + b0, y1 = d[mt][nt][1] + b1;
            float y2 = d[mt][nt][2] + b0, y3 = d[mt][nt][3] + b1;
            if (khi) {
                uint32_t hi0 = bfpack(y1, y0);
                uint32_t lo0 = bfpack(y1 - bfhi_f(hi0), y0 - bflo_f(hi0));
                uint32_t hi1 = bfpack(y3, y2);
                uint32_t lo1 = bfpack(y3 - bfhi_f(hi1), y2 - bflo_f(hi1));
                khi[(size_t)ra  * 128 + (c >> 1)] = hi0;
                klo[(size_t)ra  * 128 + (c >> 1)] = lo0;
                khi[(size_t)rb2 * 128 + (c >> 1)] = hi1;
                klo[(size_t)rb2 * 128 + (c >> 1)] = lo1;
            } else {
                size_t o0 = (size_t)ra  * E_DIM + c;
                size_t o1 = (size_t)rb2 * E_DIM + c;
                if (add_residual) {
                    float2 x0 = *(const float2*)&X[o0];
                    float2 x1 = *(const float2*)&X[o1];
                    y0 += x0.x; y1 += x0.y; y2 += x1.x; y3 += x1.y;
                }
                *(float2*)&Y[o0] = make_float2(y0, y1);
                *(float2*)&Y[o1] = make_float2(y2, y3);
            }
        }
    }
}

__global__ __launch_bounds__(256, 2) void proj_qk_kernel(
    const float* __restrict__ Xq, const float* __restrict__ Wq, const float* __restrict__ bq,
    const float* __restrict__ Xk, const float* __restrict__ Wk, const float* __restrict__ bk,
    float* __restrict__ Yq, uint32_t* __restrict__ khi, uint32_t* __restrict__ klo)
{
    int r0 = blockIdx.x * 32;
    if (blockIdx.y == 0) proj_tc_body(Xq, Wq, bq, Yq, nullptr, nullptr, 0, r0);
    else                 proj_tc_body(Xk, Wk, bk, nullptr, khi, klo, 0, r0);
}

__global__ __launch_bounds__(256, 2) void proj_o_kernel(
    const float* __restrict__ X, const float* __restrict__ W,
    const float* __restrict__ bias, float* __restrict__ Y)
{
    proj_tc_body(X, W, bias, Y, nullptr, nullptr, 1, blockIdx.x * 32);
}

// ---------------------------------------------------------------------------
// attn_tc_kernel (R11 version): 512 threads, 2-stage cp.async.
// Pass1: 1-term bf16 QK on 128-row s-tiles (2x 64-row sub-steps).
// Pass2: 2-split bf16 QK + 1xTF32 PV on 32-row s-tiles.
// ---------------------------------------------------------------------------
__global__ __launch_bounds__(512, 1) void attn_tc_kernel(
    const float* __restrict__ value,
    float* __restrict__ avgw,
    float* __restrict__ attn_out)
{
    extern __shared__ uint32_t smu[];
    float* Ps = (float*)(smu + PS_OFF);
    __shared__ float Lsh[16][32][4];

    const uint32_t sb = (uint32_t)__cvta_generic_to_shared(smu);

    const int tid  = threadIdx.x;
    const int wid  = tid >> 5;
    const int h    = wid & 7;
    const int sh   = wid >> 3;
    const int lane = tid & 31;
    const int g    = lane >> 2;
    const int tig  = lane & 3;
    const int t0   = blockIdx.x * 32;
    const int b    = blockIdx.y;
    const int hb   = h * DH;
    const int hw   = hb >> 1;

    // ---- Q fragments: bf16 2-split ----
    uint32_t qh[2][2][4], ql[2][2][4];
#pragma unroll
    for (int mt = 0; mt < 2; mt++) {
#pragma unroll
        for (int jc = 0; jc < 2; jc++) {
            int r = t0 + mt * 16 + g;
            int c = hb + jc * 16 + 2 * tig;
            float2 v0 = *(const float2*)&g_qproj[((size_t)r       * B_DIM + b) * E_DIM + c];
            float2 v1 = *(const float2*)&g_qproj[((size_t)(r + 8) * B_DIM + b) * E_DIM + c];
            float2 v2 = *(const float2*)&g_qproj[((size_t)r       * B_DIM + b) * E_DIM + c + 8];
            float2 v3 = *(const float2*)&g_qproj[((size_t)(r + 8) * B_DIM + b) * E_DIM + c + 8];
            qh[mt][jc][0] = bfpack(v0.y, v0.x);
            qh[mt][jc][1] = bfpack(v1.y, v1.x);
            qh[mt][jc][2] = bfpack(v2.y, v2.x);
            qh[mt][jc][3] = bfpack(v3.y, v3.x);
            ql[mt][jc][0] = bfpack(v0.y - bfhi_f(qh[mt][jc][0]), v0.x - bflo_f(qh[mt][jc][0]));
            ql[mt][jc][1] = bfpack(v1.y - bfhi_f(qh[mt][jc][1]), v1.x - bflo_f(qh[mt][jc][1]));
            ql[mt][jc][2] = bfpack(v2.y - bfhi_f(qh[mt][jc][2]), v2.x - bflo_f(qh[mt][jc][2]));
            ql[mt][jc][3] = bfpack(v3.y - bfhi_f(qh[mt][jc][3]), v3.x - bflo_f(qh[mt][jc][3]));
        }
    }

    // ========= pass 1: lsum via 1-term bf16 QK, 128-row tiles =========
    float lsum[4] = {0.f, 0.f, 0.f, 0.f};
    {
        const int NT1 = S_DIM / 128;          // 16

#pragma unroll
        for (int i = 0; i < 8; i++) {
            int idx = tid + i * 512;
            int row = idx >> 5, c = idx & 31;
            cpa16(sb + (uint32_t)(row * KWSTR + c * 4) * 4,
                  &g_khi[((size_t)row * B_DIM + b) * 128 + c * 4]);
        }
        CP_COMMIT();

        for (int t = 0; t < NT1; t++) {
            CP_WAIT0();
            __syncthreads();
            if (t + 1 < NT1) {
                int s0n = (t + 1) * 128;
                uint32_t dst = sb + (uint32_t)(((t + 1) & 1) * P1STAGE) * 4;
#pragma unroll
                for (int i = 0; i < 8; i++) {
                    int idx = tid + i * 512;
                    int row = idx >> 5, c = idx & 31;
                    cpa16(dst + (uint32_t)(row * KWSTR + c * 4) * 4,
                          &g_khi[((size_t)(s0n + row) * B_DIM + b) * 128 + c * 4]);
                }
            }
            CP_COMMIT();

            const uint32_t* Kh = smu + (t & 1) * P1STAGE;

#pragma unroll
            for (int sub = 0; sub < 2; sub++) {
                const int soW1 = sub * 64 + sh * 32;
                float d[2][4][4];
#pragma unroll
                for (int mt = 0; mt < 2; mt++)
#pragma unroll
                    for (int nt = 0; nt < 4; nt++)
#pragma unroll
                        for (int r = 0; r < 4; r++) d[mt][nt][r] = 0.f;

#pragma unroll
                for (int jc = 0; jc < 2; jc++) {
                    uint32_t bh[4][2];
#pragma unroll
                    for (int nt = 0; nt < 4; nt++) {
                        int base = (soW1 + nt * 8 + g) * KWSTR + hw + jc * 8 + tig;
                        bh[nt][0] = Kh[base]; bh[nt][1] = Kh[base + 4];
                    }
#pragma unroll
                    for (int nt = 0; nt < 4; nt++) {
                        mma_bf16(d[0][nt], qh[0][jc], bh[nt]);
                        mma_bf16(d[1][nt], qh[1][jc], bh[nt]);
                    }
                }
#pragma unroll
                for (int mt = 0; mt < 2; mt++)
#pragma unroll
                    for (int nt = 0; nt < 4; nt++)
#pragma unroll
                        for (int r = 0; r < 4; r++)
                            lsum[mt * 2 + (r >> 1)] += ex2f(d[mt][nt][r] * SCLOG2E);
            }
        }
    }
#pragma unroll
    for (int r = 0; r < 4; r++) {
        lsum[r] += __shfl_xor_sync(0xffffffffu, lsum[r], 1);
        lsum[r] += __shfl_xor_sync(0xffffffffu, lsum[r], 2);
    }
#pragma unroll
    for (int r = 0; r < 4; r++) Lsh[wid][lane][r] = lsum[r];
    __syncthreads();
    float inv[4];
#pragma unroll
    for (int r = 0; r < 4; r++) inv[r] = 1.0f / (lsum[r] + Lsh[wid ^ 8][lane][r]);

    // ================= pass 2 =================
    float o[2][4][4];
#pragma unroll
    for (int mt = 0; mt < 2; mt++)
#pragma unroll
        for (int nd = 0; nd < 4; nd++)
#pragma unroll
            for (int r = 0; r < 4; r++) o[mt][nd][r] = 0.f;

    const int soW = sh * 16;
    const int NT = S_DIM / 32;

    {
        uint32_t dkh = sb + (uint32_t)(KH_OFF) * 4;
        uint32_t dkl = sb + (uint32_t)(KL_OFF) * 4;
        uint32_t dv  = sb + (uint32_t)(V_OFF) * 4;
#pragma unroll
        for (int i = 0; i < 2; i++) {
            int idx = tid + i * 512;
            int row = idx >> 5, c = idx & 31;
            size_t gsrc = ((size_t)row * B_DIM + b) * 128 + c * 4;
            cpa16(dkh + (uint32_t)(row * KWSTR + c * 4) * 4, &g_khi[gsrc]);
            cpa16(dkl + (uint32_t)(row * KWSTR + c * 4) * 4, &g_klo[gsrc]);
        }
#pragma unroll
        for (int i = 0; i < 4; i++) {
            int idx = tid + i * 512;
            int row = idx >> 6, c = idx & 63;
            cpa16(dv + (uint32_t)(row * VSTR + c * 4) * 4,
                  &value[((size_t)row * B_DIM + b) * 256 + c * 4]);
        }
    }
    CP_COMMIT();

    for (int t = 0; t < NT; t++) {
        CP_WAIT0();
        __syncthreads();
        if (t + 1 < NT) {
            int nst = (t + 1) & 1;
            int s0n = (t + 1) * 32;
            uint32_t dkh = sb + (uint32_t)(KH_OFF + nst * 32 * KWSTR) * 4;
            uint32_t dkl = sb + (uint32_t)(KL_OFF + nst * 32 * KWSTR) * 4;
            uint32_t dv  = sb + (uint32_t)(V_OFF  + nst * 32 * VSTR) * 4;
#pragma unroll
            for (int i = 0; i < 2; i++) {
                int idx = tid + i * 512;
                int row = idx >> 5, c = idx & 31;
                size_t gsrc = ((size_t)(s0n + row) * B_DIM + b) * 128 + c * 4;
                cpa16(dkh + (uint32_t)(row * KWSTR + c * 4) * 4, &g_khi[gsrc]);
                cpa16(dkl + (uint32_t)(row * KWSTR + c * 4) * 4, &g_klo[gsrc]);
            }
#pragma unroll
            for (int i = 0; i < 4; i++) {
                int idx = tid + i * 512;
                int row = idx >> 6, c = idx & 63;
                cpa16(dv + (uint32_t)(row * VSTR + c * 4) * 4,
                      &value[((size_t)(s0n + row) * B_DIM + b) * 256 + c * 4]);
            }
        }
        CP_COMMIT();

        const int st = t & 1;
        const uint32_t* Kh = smu + KH_OFF + st * 32 * KWSTR;
        const uint32_t* Kl = smu + KL_OFF + st * 32 * KWSTR;
        const float*    Vs = (const float*)(smu + V_OFF + st * 32 * VSTR);
        const int s0 = t * 32;

        float d[2][2][4];
#pragma unroll
        for (int mt = 0; mt < 2; mt++)
#pragma unroll
            for (int nt = 0; nt < 2; nt++)
#pragma unroll
                for (int r = 0; r < 4; r++) d[mt][nt][r] = 0.f;

#pragma unroll
        for (int jc = 0; jc < 2; jc++) {
            uint32_t bh[2][2], bl[2][2];
#pragma unroll
            for (int nt = 0; nt < 2; nt++) {
                int base = (soW + nt * 8 + g) * KWSTR + hw + jc * 8 + tig;
                bh[nt][0] = Kh[base]; bh[nt][1] = Kh[base + 4];
                bl[nt][0] = Kl[base]; bl[nt][1] = Kl[base + 4];
            }
#pragma unroll
            for (int nt = 0; nt < 2; nt++) {
                mma_bf16(d[0][nt], qh[0][jc], bh[nt]);
                mma_bf16(d[1][nt], qh[1][jc], bh[nt]);
            }
#pragma unroll
            for (int nt = 0; nt < 2; nt++) {
                mma_bf16(d[0][nt], ql[0][jc], bh[nt]);
                mma_bf16(d[1][nt], ql[1][jc], bh[nt]);
            }
#pragma unroll
            for (int nt = 0; nt < 2; nt++) {
                mma_bf16(d[0][nt], qh[0][jc], bl[nt]);
                mma_bf16(d[1][nt], qh[1][jc], bl[nt]);
            }
        }

        // normalize, stage p into Ps
#pragma unroll
        for (int mt = 0; mt < 2; mt++) {
#pragma unroll
            for (int nt = 0; nt < 2; nt++) {
                float p0 = ex2f(d[mt][nt][0] * SCLOG2E) * inv[mt * 2 + 0];
                float p1 = ex2f(d[mt][nt][1] * SCLOG2E) * inv[mt * 2 + 0];
                float p2 = ex2f(d[mt][nt][2] * SCLOG2E) * inv[mt * 2 + 1];
                float p3 = ex2f(d[mt][nt][3] * SCLOG2E) * inv[mt * 2 + 1];
                int scol = soW + nt * 8 + 2 * tig;
                *(float2*)&Ps[h * PHEAD + (mt * 16 + g)     * PSTR + scol] = make_float2(p0, p1);
                *(float2*)&Ps[h * PHEAD + (mt * 16 + g + 8) * PSTR + scol] = make_float2(p2, p3);
            }
        }
        __syncwarp();

        // PV over this warp's 16 s-rows: 1xTF32
#pragma unroll
        for (int ks = 0; ks < 2; ks++) {
            uint32_t a[2][4];
            int sc = soW + ks * 8 + tig;
#pragma unroll
            for (int mt = 0; mt < 2; mt++) {
                int rb = mt * 16;
                a[mt][0] = f2tf32(Ps[h * PHEAD + (rb + g)     * PSTR + sc]);
                a[mt][1] = f2tf32(Ps[h * PHEAD + (rb + g + 8) * PSTR + sc]);
                a[mt][2] = f2tf32(Ps[h * PHEAD + (rb + g)     * PSTR + sc + 4]);
                a[mt][3] = f2tf32(Ps[h * PHEAD + (rb + g + 8) * PSTR + sc + 4]);
            }
#pragma unroll
            for (int nd = 0; nd < 4; nd++) {
                uint32_t bb[2];
                bb[0] = f2tf32(Vs[(soW + ks * 8 + tig)     * VSTR + hb + nd * 8 + g]);
                bb[1] = f2tf32(Vs[(soW + ks * 8 + tig + 4) * VSTR + hb + nd * 8 + g]);
                mma_tf32(o[0][nd], a[0], bb);
                mma_tf32(o[1][nd], a[1], bb);
            }
        }
        __syncthreads();

        // avg_weights tile [32 t x 32 s]
        {
            int row = tid >> 4;
            int sb2 = (tid & 15) * 2;
            float2 acc = make_float2(0.f, 0.f);
#pragma unroll
            for (int hh = 0; hh < 8; hh++) {
                float2 x = *(const float2*)&Ps[hh * PHEAD + row * PSTR + sb2];
                acc.x += x.x; acc.y += x.y;
            }
            acc.x *= 0.125f; acc.y *= 0.125f;
            size_t oo = (size_t)b * T_DIM * S_DIM + (size_t)(t0 + row) * S_DIM + s0 + sb2;
            *(float2*)&avgw[oo] = acc;
        }
    }

    // ---- merge s-half partial PV accumulators, write attn_out ----
    __syncthreads();
    float* Os = Ps;
    if (sh == 1) {
#pragma unroll
        for (int mt = 0; mt < 2; mt++)
#pragma unroll
            for (int nd = 0; nd < 4; nd++)
#pragma unroll
                for (int r = 0; r < 4; r++)
                    Os[(h * 32 + lane) * 33 + mt * 16 + nd * 4 + r] = o[mt][nd][r];
    }
    __syncthreads();
    if (sh == 0) {
#pragma unroll
        for (int mt = 0; mt < 2; mt++) {
#pragma unroll
            for (int nd = 0; nd < 4; nd++) {
#pragma unroll
                for (int r = 0; r < 4; r++)
                    o[mt][nd][r] += Os[(h * 32 + lane) * 33 + mt * 16 + nd * 4 + r];
                int col = hb + nd * 8 + 2 * tig;
                size_t b0 = ((size_t)(t0 + mt * 16 + g)     * B_DIM + b) * E_DIM + col;
                size_t b1 = ((size_t)(t0 + mt * 16 + g + 8) * B_DIM + b) * E_DIM + col;
                *(float2*)&attn_out[b0] = make_float2(o[mt][nd][0], o[mt][nd][1]);
                *(float2*)&attn_out[b1] = make_float2(o[mt][nd][2], o[mt][nd][3]);
            }
        }
    }
}

// ---------------------------------------------------------------------------
extern "C" void kernel_launch(void* const* d_in, const int* in_sizes, int n_in,
                              void* d_out, int out_size)
{
    (void)in_sizes; (void)n_in; (void)out_size;

    const float* query = (const float*)d_in[0];
    const float* key   = (const float*)d_in[1];
    const float* value = (const float*)d_in[2];
    const float* Wq    = (const float*)d_in[3];
    const float* bq    = (const float*)d_in[4];
    const float* Wk    = (const float*)d_in[5];
    const float* bk    = (const float*)d_in[6];
    const float* Wo    = (const float*)d_in[7];
    const float* bo    = (const float*)d_in[8];

    float* out  = (float*)d_out;
    float* avgw = out + (size_t)T_DIM * B_DIM * E_DIM;

    float *qp = nullptr, *ao = nullptr;
    uint32_t *khi = nullptr, *klo = nullptr;
    cudaGetSymbolAddress((void**)&qp,  g_qproj);
    cudaGetSymbolAddress((void**)&khi, g_khi);
    cudaGetSymbolAddress((void**)&klo, g_klo);
    cudaGetSymbolAddress((void**)&ao,  g_attnout);

    const int rows_blocks = (T_DIM * B_DIM) / 32;   // 128
    const int pj_smem = PJ_FLOATS * 4;              // 92160

    cudaFuncSetAttribute(proj_qk_kernel, cudaFuncAttributeMaxDynamicSharedMemorySize, pj_smem);
    cudaFuncSetAttribute(proj_o_kernel,  cudaFuncAttributeMaxDynamicSharedMemorySize, pj_smem);

    proj_qk_kernel<<<dim3(rows_blocks, 2), 256, pj_smem>>>(query, Wq, bq, key, Wk, bk, qp, khi, klo);

    const int smem_bytes = SMEM_WORDS * 4;  // 172032
    cudaFuncSetAttribute(attn_tc_kernel, cudaFuncAttributeMaxDynamicSharedMemorySize, smem_bytes);
    attn_tc_kernel<<<dim3(T_DIM / 32, B_DIM), 512, smem_bytes>>>(value, avgw, ao);

    proj_o_kernel<<<rows_blocks, 256, pj_smem>>>(ao, Wo, bo, out);
}

// round 15
// speedup vs baseline: 1.0967x; 1.0835x over previous
#include <cuda_runtime.h>
#include <cstdint>

#define T_DIM 2048
#define S_DIM 2048
#define B_DIM 2
#define E_DIM 256
#define H_DIM 8
#define DH    32
#define SCLOG2E 0.25503511091247115f   // (1/sqrt(32)) * log2(e)

// Scratch (device globals: no allocation allowed in kernel_launch)
__device__ float    g_qproj[(size_t)T_DIM * B_DIM * E_DIM];
__device__ uint32_t g_khi[(size_t)S_DIM * B_DIM * (E_DIM / 2)];  // packed bf16x2 hi
__device__ uint32_t g_klo[(size_t)S_DIM * B_DIM * (E_DIM / 2)];  // packed bf16x2 lo
__device__ float    g_attnout[(size_t)T_DIM * B_DIM * E_DIM];

// ---------------- conversion helpers ----------------
__device__ __forceinline__ uint32_t f2tf32(float f) {
    uint32_t r; asm("cvt.rna.tf32.f32 %0, %1;" : "=r"(r) : "f"(f)); return r;
}
__device__ __forceinline__ float tf2f(uint32_t u) { return __uint_as_float(u); }
__device__ __forceinline__ float ex2f(float x) {
    float y; asm("ex2.approx.f32 %0, %1;" : "=f"(y) : "f"(x)); return y;
}
__device__ __forceinline__ uint32_t bfpack(float hi, float lo) {
    uint32_t r; asm("cvt.rn.bf16x2.f32 %0, %1, %2;" : "=r"(r) : "f"(hi), "f"(lo)); return r;
}
__device__ __forceinline__ float bflo_f(uint32_t u) { return __uint_as_float(u << 16); }
__device__ __forceinline__ float bfhi_f(uint32_t u) { return __uint_as_float(u & 0xffff0000u); }

__device__ __forceinline__ void mma_tf32(float* d, const uint32_t* a, const uint32_t* b) {
    asm volatile(
        "mma.sync.aligned.m16n8k8.row.col.f32.tf32.tf32.f32 "
        "{%0,%1,%2,%3}, {%4,%5,%6,%7}, {%8,%9}, {%0,%1,%2,%3};"
        : "+f"(d[0]), "+f"(d[1]), "+f"(d[2]), "+f"(d[3])
        : "r"(a[0]), "r"(a[1]), "r"(a[2]), "r"(a[3]), "r"(b[0]), "r"(b[1]));
}
__device__ __forceinline__ void mma_bf16(float* d, const uint32_t* a, const uint32_t* b) {
    asm volatile(
        "mma.sync.aligned.m16n8k16.row.col.f32.bf16.bf16.f32 "
        "{%0,%1,%2,%3}, {%4,%5,%6,%7}, {%8,%9}, {%0,%1,%2,%3};"
        : "+f"(d[0]), "+f"(d[1]), "+f"(d[2]), "+f"(d[3])
        : "r"(a[0]), "r"(a[1]), "r"(a[2]), "r"(a[3]), "r"(b[0]), "r"(b[1]));
}

// ---------------- cp.async helpers (.ca — measured best) ----------------
__device__ __forceinline__ void cpa16(uint32_t s, const void* g) {
    asm volatile("cp.async.ca.shared.global [%0], [%1], 16;" :: "r"(s), "l"(g) : "memory");
}
#define CP_COMMIT() asm volatile("cp.async.commit_group;" ::: "memory")
#define CP_WAIT0()  asm volatile("cp.async.wait_group 0;" ::: "memory")

// attn smem layout (words)
#define KWSTR 132
#define VSTR  264
#define PSTR  36
#define PHEAD (32 * PSTR)
#define KH_OFF 0
#define KL_OFF (2 * 32 * KWSTR)            //  8448
#define V_OFF  (4 * 32 * KWSTR)            // 16896
#define PS_OFF (V_OFF + 2 * 32 * VSTR)     // 33792
#define SMEM_WORDS (PS_OFF + 8 * 32 * PSTR) // 43008 -> 172032 B
#define P1STAGE (128 * KWSTR)              // 16896 (pass1 Kh stages fill [0,PS_OFF))

// proj smem layout (floats): Ws[2][256*36] | Xh[2][32*36] | Xl[2][32*36]
#define PJ_WSZ   (256 * 36)
#define PJ_XSZ   (32 * 36)
#define PJ_XH0   (2 * PJ_WSZ)
#define PJ_XL0   (2 * PJ_WSZ + 2 * PJ_XSZ)
#define PJ_FLOATS (2 * PJ_WSZ + 4 * PJ_XSZ) // 23040 -> 92160 B

// ---------------------------------------------------------------------------
// proj body: 3xTF32, 32 rows x 256 cols per block, W split in-kernel,
// 2-stage cp.async pipeline (R11 measured-best version).
// ---------------------------------------------------------------------------
__device__ __forceinline__ void proj_tc_body(
    const float* __restrict__ X, const float* __restrict__ W,
    const float* __restrict__ bias, float* __restrict__ Y,
    uint32_t* __restrict__ khi, uint32_t* __restrict__ klo,
    int add_residual, int r0)
{
    extern __shared__ float pj[];
    const uint32_t sbase = (uint32_t)__cvta_generic_to_shared(pj);

    const int tid  = threadIdx.x;
    const int w    = tid >> 5;
    const int lane = tid & 31;
    const int g    = lane >> 2;
    const int tig  = lane & 3;

    float d[2][4][4];
#pragma unroll
    for (int mt = 0; mt < 2; mt++)
#pragma unroll
        for (int nt = 0; nt < 4; nt++)
#pragma unroll
            for (int r = 0; r < 4; r++) d[mt][nt][r] = 0.f;

    float xv[4];
#pragma unroll
    for (int i = 0; i < 8; i++) {
        int idx = tid + i * 256;
        int n = idx >> 3, c4 = (idx & 7) * 4;
        cpa16(sbase + (uint32_t)(n * 36 + c4) * 4, &W[(size_t)n * E_DIM + c4]);
    }
    CP_COMMIT();
#pragma unroll
    for (int i = 0; i < 4; i++) {
        int idx = tid + i * 256;
        int r = idx >> 5, e = idx & 31;
        xv[i] = X[(size_t)(r0 + r) * E_DIM + e];
    }

    for (int c = 0; c < 8; c++) {
        const int st = c & 1;
        float* Ws = pj + st * PJ_WSZ;
        float* Xh = pj + PJ_XH0 + st * PJ_XSZ;
        float* Xl = pj + PJ_XL0 + st * PJ_XSZ;

#pragma unroll
        for (int i = 0; i < 4; i++) {
            int idx = tid + i * 256;
            int r = idx >> 5, e = idx & 31;
            float hh = tf2f(f2tf32(xv[i]));
            Xh[r * 36 + e] = hh;
            Xl[r * 36 + e] = xv[i] - hh;
        }
        CP_WAIT0();
        __syncthreads();

        if (c + 1 < 8) {
            int e0n = (c + 1) * 32;
            uint32_t dst = sbase + (uint32_t)((st ^ 1) * PJ_WSZ) * 4;
#pragma unroll
            for (int i = 0; i < 8; i++) {
                int idx = tid + i * 256;
                int n = idx >> 3, c4 = (idx & 7) * 4;
                cpa16(dst + (uint32_t)(n * 36 + c4) * 4, &W[(size_t)n * E_DIM + e0n + c4]);
            }
            CP_COMMIT();
#pragma unroll
            for (int i = 0; i < 4; i++) {
                int idx = tid + i * 256;
                int r = idx >> 5, e = idx & 31;
                xv[i] = X[(size_t)(r0 + r) * E_DIM + e0n + e];
            }
        }

#pragma unroll
        for (int k8 = 0; k8 < 4; k8++) {
            uint32_t ah[2][4], al[2][4];
#pragma unroll
            for (int mt = 0; mt < 2; mt++) {
                int rA = mt * 16 + g;
                ah[mt][0] = __float_as_uint(Xh[rA * 36 + k8 * 8 + tig]);
                ah[mt][1] = __float_as_uint(Xh[(rA + 8) * 36 + k8 * 8 + tig]);
                ah[mt][2] = __float_as_uint(Xh[rA * 36 + k8 * 8 + tig + 4]);
                ah[mt][3] = __float_as_uint(Xh[(rA + 8) * 36 + k8 * 8 + tig + 4]);
                al[mt][0] = f2tf32(Xl[rA * 36 + k8 * 8 + tig]);
                al[mt][1] = f2tf32(Xl[(rA + 8) * 36 + k8 * 8 + tig]);
                al[mt][2] = f2tf32(Xl[rA * 36 + k8 * 8 + tig + 4]);
                al[mt][3] = f2tf32(Xl[(rA + 8) * 36 + k8 * 8 + tig + 4]);
            }
#pragma unroll
            for (int nt = 0; nt < 4; nt++) {
                int n = w * 32 + nt * 8 + g;
                float w0 = Ws[n * 36 + k8 * 8 + tig], w1 = Ws[n * 36 + k8 * 8 + tig + 4];
                uint32_t bh[2], bl[2];
                bh[0] = f2tf32(w0); bl[0] = f2tf32(w0 - tf2f(bh[0]));
                bh[1] = f2tf32(w1); bl[1] = f2tf32(w1 - tf2f(bh[1]));
                mma_tf32(d[0][nt], ah[0], bh);
                mma_tf32(d[1][nt], ah[1], bh);
                mma_tf32(d[0][nt], al[0], bh);
                mma_tf32(d[1][nt], al[1], bh);
                mma_tf32(d[0][nt], ah[0], bl);
                mma_tf32(d[1][nt], ah[1], bl);
            }
        }
    }

#pragma unroll
    for (int mt = 0; mt < 2; mt++) {
#pragma unroll
        for (int nt = 0; nt < 4; nt++) {
            int c = w * 32 + nt * 8 + 2 * tig;
            float b0 = __ldg(&bias[c]), b1 = __ldg(&bias[c + 1]);
            int ra = r0 + mt * 16 + g;
            int rb2 = ra + 8;
            float y0 = d[mt][nt][0] + b0, y1 = d[mt][nt][1] + b1;
            float y2 = d[mt][nt][2] + b0, y3 = d[mt][nt][3] + b1;
            if (khi) {
                uint32_t hi0 = bfpack(y1, y0);
                uint32_t lo0 = bfpack(y1 - bfhi_f(hi0), y0 - bflo_f(hi0));
                uint32_t hi1 = bfpack(y3, y2);
                uint32_t lo1 = bfpack(y3 - bfhi_f(hi1), y2 - bflo_f(hi1));
                khi[(size_t)ra  * 128 + (c >> 1)] = hi0;
                klo[(size_t)ra  * 128 + (c >> 1)] = lo0;
                khi[(size_t)rb2 * 128 + (c >> 1)] = hi1;
                klo[(size_t)rb2 * 128 + (c >> 1)] = lo1;
            } else {
                size_t o0 = (size_t)ra  * E_DIM + c;
                size_t o1 = (size_t)rb2 * E_DIM + c;
                if (add_residual) {
                    float2 x0 = *(const float2*)&X[o0];
                    float2 x1 = *(const float2*)&X[o1];
                    y0 += x0.x; y1 += x0.y; y2 += x1.x; y3 += x1.y;
                }
                *(float2*)&Y[o0] = make_float2(y0, y1);
                *(float2*)&Y[o1] = make_float2(y2, y3);
            }
        }
    }
}

__global__ __launch_bounds__(256, 2) void proj_qk_kernel(
    const float* __restrict__ Xq, const float* __restrict__ Wq, const float* __restrict__ bq,
    const float* __restrict__ Xk, const float* __restrict__ Wk, const float* __restrict__ bk,
    float* __restrict__ Yq, uint32_t* __restrict__ khi, uint32_t* __restrict__ klo)
{
    int r0 = blockIdx.x * 32;
    if (blockIdx.y == 0) proj_tc_body(Xq, Wq, bq, Yq, nullptr, nullptr, 0, r0);
    else                 proj_tc_body(Xk, Wk, bk, nullptr, khi, klo, 0, r0);
}

__global__ __launch_bounds__(256, 2) void proj_o_kernel(
    const float* __restrict__ X, const float* __restrict__ W,
    const float* __restrict__ bias, float* __restrict__ Y)
{
    proj_tc_body(X, W, bias, Y, nullptr, nullptr, 1, blockIdx.x * 32);
}

// ---------------------------------------------------------------------------
// attn_tc_kernel (R11 measured-best): 512 threads, 2-stage cp.async.
// Pass1: 1-term bf16 QK on 128-row s-tiles (2x 64-row sub-steps).
// Pass2: 2-split bf16 QK + 1xTF32 PV on 32-row s-tiles.
// ---------------------------------------------------------------------------
__global__ __launch_bounds__(512, 1) void attn_tc_kernel(
    const float* __restrict__ value,
    float* __restrict__ avgw,
    float* __restrict__ attn_out)
{
    extern __shared__ uint32_t smu[];
    float* Ps = (float*)(smu + PS_OFF);
    __shared__ float Lsh[16][32][4];

    const uint32_t sb = (uint32_t)__cvta_generic_to_shared(smu);

    const int tid  = threadIdx.x;
    const int wid  = tid >> 5;
    const int h    = wid & 7;
    const int sh   = wid >> 3;
    const int lane = tid & 31;
    const int g    = lane >> 2;
    const int tig  = lane & 3;
    const int t0   = blockIdx.x * 32;
    const int b    = blockIdx.y;
    const int hb   = h * DH;
    const int hw   = hb >> 1;

    // ---- Q fragments: bf16 2-split ----
    uint32_t qh[2][2][4], ql[2][2][4];
#pragma unroll
    for (int mt = 0; mt < 2; mt++) {
#pragma unroll
        for (int jc = 0; jc < 2; jc++) {
            int r = t0 + mt * 16 + g;
            int c = hb + jc * 16 + 2 * tig;
            float2 v0 = *(const float2*)&g_qproj[((size_t)r       * B_DIM + b) * E_DIM + c];
            float2 v1 = *(const float2*)&g_qproj[((size_t)(r + 8) * B_DIM + b) * E_DIM + c];
            float2 v2 = *(const float2*)&g_qproj[((size_t)r       * B_DIM + b) * E_DIM + c + 8];
            float2 v3 = *(const float2*)&g_qproj[((size_t)(r + 8) * B_DIM + b) * E_DIM + c + 8];
            qh[mt][jc][0] = bfpack(v0.y, v0.x);
            qh[mt][jc][1] = bfpack(v1.y, v1.x);
            qh[mt][jc][2] = bfpack(v2.y, v2.x);
            qh[mt][jc][3] = bfpack(v3.y, v3.x);
            ql[mt][jc][0] = bfpack(v0.y - bfhi_f(qh[mt][jc][0]), v0.x - bflo_f(qh[mt][jc][0]));
            ql[mt][jc][1] = bfpack(v1.y - bfhi_f(qh[mt][jc][1]), v1.x - bflo_f(qh[mt][jc][1]));
            ql[mt][jc][2] = bfpack(v2.y - bfhi_f(qh[mt][jc][2]), v2.x - bflo_f(qh[mt][jc][2]));
            ql[mt][jc][3] = bfpack(v3.y - bfhi_f(qh[mt][jc][3]), v3.x - bflo_f(qh[mt][jc][3]));
        }
    }

    // ========= pass 1: lsum via 1-term bf16 QK, 128-row tiles =========
    float lsum[4] = {0.f, 0.f, 0.f, 0.f};
    {
        const int NT1 = S_DIM / 128;          // 16

#pragma unroll
        for (int i = 0; i < 8; i++) {
            int idx = tid + i * 512;
            int row = idx >> 5, c = idx & 31;
            cpa16(sb + (uint32_t)(row * KWSTR + c * 4) * 4,
                  &g_khi[((size_t)row * B_DIM + b) * 128 + c * 4]);
        }
        CP_COMMIT();

        for (int t = 0; t < NT1; t++) {
            CP_WAIT0();
            __syncthreads();
            if (t + 1 < NT1) {
                int s0n = (t + 1) * 128;
                uint32_t dst = sb + (uint32_t)(((t + 1) & 1) * P1STAGE) * 4;
#pragma unroll
                for (int i = 0; i < 8; i++) {
                    int idx = tid + i * 512;
                    int row = idx >> 5, c = idx & 31;
                    cpa16(dst + (uint32_t)(row * KWSTR + c * 4) * 4,
                          &g_khi[((size_t)(s0n + row) * B_DIM + b) * 128 + c * 4]);
                }
            }
            CP_COMMIT();

            const uint32_t* Kh = smu + (t & 1) * P1STAGE;

#pragma unroll
            for (int sub = 0; sub < 2; sub++) {
                const int soW1 = sub * 64 + sh * 32;
                float d[2][4][4];
#pragma unroll
                for (int mt = 0; mt < 2; mt++)
#pragma unroll
                    for (int nt = 0; nt < 4; nt++)
#pragma unroll
                        for (int r = 0; r < 4; r++) d[mt][nt][r] = 0.f;

#pragma unroll
                for (int jc = 0; jc < 2; jc++) {
                    uint32_t bh[4][2];
#pragma unroll
                    for (int nt = 0; nt < 4; nt++) {
                        int base = (soW1 + nt * 8 + g) * KWSTR + hw + jc * 8 + tig;
                        bh[nt][0] = Kh[base]; bh[nt][1] = Kh[base + 4];
                    }
#pragma unroll
                    for (int nt = 0; nt < 4; nt++) {
                        mma_bf16(d[0][nt], qh[0][jc], bh[nt]);
                        mma_bf16(d[1][nt], qh[1][jc], bh[nt]);
                    }
                }
#pragma unroll
                for (int mt = 0; mt < 2; mt++)
#pragma unroll
                    for (int nt = 0; nt < 4; nt++)
#pragma unroll
                        for (int r = 0; r < 4; r++)
                            lsum[mt * 2 + (r >> 1)] += ex2f(d[mt][nt][r] * SCLOG2E);
            }
        }
    }
#pragma unroll
    for (int r = 0; r < 4; r++) {
        lsum[r] += __shfl_xor_sync(0xffffffffu, lsum[r], 1);
        lsum[r] += __shfl_xor_sync(0xffffffffu, lsum[r], 2);
    }
#pragma unroll
    for (int r = 0; r < 4; r++) Lsh[wid][lane][r] = lsum[r];
    __syncthreads();
    float inv[4];
#pragma unroll
    for (int r = 0; r < 4; r++) inv[r] = 1.0f / (lsum[r] + Lsh[wid ^ 8][lane][r]);

    // ================= pass 2 =================
    float o[2][4][4];
#pragma unroll
    for (int mt = 0; mt < 2; mt++)
#pragma unroll
        for (int nd = 0; nd < 4; nd++)
#pragma unroll
            for (int r = 0; r < 4; r++) o[mt][nd][r] = 0.f;

    const int soW = sh * 16;
    const int NT = S_DIM / 32;

    {
        uint32_t dkh = sb + (uint32_t)(KH_OFF) * 4;
        uint32_t dkl = sb + (uint32_t)(KL_OFF) * 4;
        uint32_t dv  = sb + (uint32_t)(V_OFF) * 4;
#pragma unroll
        for (int i = 0; i < 2; i++) {
            int idx = tid + i * 512;
            int row = idx >> 5, c = idx & 31;
            size_t gsrc = ((size_t)row * B_DIM + b) * 128 + c * 4;
            cpa16(dkh + (uint32_t)(row * KWSTR + c * 4) * 4, &g_khi[gsrc]);
            cpa16(dkl + (uint32_t)(row * KWSTR + c * 4) * 4, &g_klo[gsrc]);
        }
#pragma unroll
        for (int i = 0; i < 4; i++) {
            int idx = tid + i * 512;
            int row = idx >> 6, c = idx & 63;
            cpa16(dv + (uint32_t)(row * VSTR + c * 4) * 4,
                  &value[((size_t)row * B_DIM + b) * 256 + c * 4]);
        }
    }
    CP_COMMIT();

    for (int t = 0; t < NT; t++) {
        CP_WAIT0();
        __syncthreads();
        if (t + 1 < NT) {
            int nst = (t + 1) & 1;
            int s0n = (t + 1) * 32;
            uint32_t dkh = sb + (uint32_t)(KH_OFF + nst * 32 * KWSTR) * 4;
            uint32_t dkl = sb + (uint32_t)(KL_OFF + nst * 32 * KWSTR) * 4;
            uint32_t dv  = sb + (uint32_t)(V_OFF  + nst * 32 * VSTR) * 4;
#pragma unroll
            for (int i = 0; i < 2; i++) {
                int idx = tid + i * 512;
                int row = idx >> 5, c = idx & 31;
                size_t gsrc = ((size_t)(s0n + row) * B_DIM + b) * 128 + c * 4;
                cpa16(dkh + (uint32_t)(row * KWSTR + c * 4) * 4, &g_khi[gsrc]);
                cpa16(dkl + (uint32_t)(row * KWSTR + c * 4) * 4, &g_klo[gsrc]);
            }
#pragma unroll
            for (int i = 0; i < 4; i++) {
                int idx = tid + i * 512;
                int row = idx >> 6, c = idx & 63;
                cpa16(dv + (uint32_t)(row * VSTR + c * 4) * 4,
                      &value[((size_t)(s0n + row) * B_DIM + b) * 256 + c * 4]);
            }
        }
        CP_COMMIT();

        const int st = t & 1;
        const uint32_t* Kh = smu + KH_OFF + st * 32 * KWSTR;
        const uint32_t* Kl = smu + KL_OFF + st * 32 * KWSTR;
        const float*    Vs = (const float*)(smu + V_OFF + st * 32 * VSTR);
        const int s0 = t * 32;

        float d[2][2][4];
#pragma unroll
        for (int mt = 0; mt < 2; mt++)
#pragma unroll
            for (int nt = 0; nt < 2; nt++)
#pragma unroll
                for (int r = 0; r < 4; r++) d[mt][nt][r] = 0.f;

#pragma unroll
        for (int jc = 0; jc < 2; jc++) {
            uint32_t bh[2][2], bl[2][2];
#pragma unroll
            for (int nt = 0; nt < 2; nt++) {
                int base = (soW + nt * 8 + g) * KWSTR + hw + jc * 8 + tig;
                bh[nt][0] = Kh[base]; bh[nt][1] = Kh[base + 4];
                bl[nt][0] = Kl[base]; bl[nt][1] = Kl[base + 4];
            }
#pragma unroll
            for (int nt = 0; nt < 2; nt++) {
                mma_bf16(d[0][nt], qh[0][jc], bh[nt]);
                mma_bf16(d[1][nt], qh[1][jc], bh[nt]);
            }
#pragma unroll
            for (int nt = 0; nt < 2; nt++) {
                mma_bf16(d[0][nt], ql[0][jc], bh[nt]);
                mma_bf16(d[1][nt], ql[1][jc], bh[nt]);
            }
#pragma unroll
            for (int nt = 0; nt < 2; nt++) {
                mma_bf16(d[0][nt], qh[0][jc], bl[nt]);
                mma_bf16(d[1][nt], qh[1][jc], bl[nt]);
            }
        }

        // normalize, stage p into Ps
#pragma unroll
        for (int mt = 0; mt < 2; mt++) {
#pragma unroll
            for (int nt = 0; nt < 2; nt++) {
                float p0 = ex2f(d[mt][nt][0] * SCLOG2E) * inv[mt * 2 + 0];
                float p1 = ex2f(d[mt][nt][1] * SCLOG2E) * inv[mt * 2 + 0];
                float p2 = ex2f(d[mt][nt][2] * SCLOG2E) * inv[mt * 2 + 1];
                float p3 = ex2f(d[mt][nt][3] * SCLOG2E) * inv[mt * 2 + 1];
                int scol = soW + nt * 8 + 2 * tig;
                *(float2*)&Ps[h * PHEAD + (mt * 16 + g)     * PSTR + scol] = make_float2(p0, p1);
                *(float2*)&Ps[h * PHEAD + (mt * 16 + g + 8) * PSTR + scol] = make_float2(p2, p3);
            }
        }
        __syncwarp();

        // PV over this warp's 16 s-rows: 1xTF32
#pragma unroll
        for (int ks = 0; ks < 2; ks++) {
            uint32_t a[2][4];
            int sc = soW + ks * 8 + tig;
#pragma unroll
            for (int mt = 0; mt < 2; mt++) {
                int rb = mt * 16;
                a[mt][0] = f2tf32(Ps[h * PHEAD + (rb + g)     * PSTR + sc]);
                a[mt][1] = f2tf32(Ps[h * PHEAD + (rb + g + 8) * PSTR + sc]);
                a[mt][2] = f2tf32(Ps[h * PHEAD + (rb + g)     * PSTR + sc + 4]);
                a[mt][3] = f2tf32(Ps[h * PHEAD + (rb + g + 8) * PSTR + sc + 4]);
            }
#pragma unroll
            for (int nd = 0; nd < 4; nd++) {
                uint32_t bb[2];
                bb[0] = f2tf32(Vs[(soW + ks * 8 + tig)     * VSTR + hb + nd * 8 + g]);
                bb[1] = f2tf32(Vs[(soW + ks * 8 + tig + 4) * VSTR + hb + nd * 8 + g]);
                mma_tf32(o[0][nd], a[0], bb);
                mma_tf32(o[1][nd], a[1], bb);
            }
        }
        __syncthreads();

        // avg_weights tile [32 t x 32 s]
        {
            int row = tid >> 4;
            int sb2 = (tid & 15) * 2;
            float2 acc = make_float2(0.f, 0.f);
#pragma unroll
            for (int hh = 0; hh < 8; hh++) {
                float2 x = *(const float2*)&Ps[hh * PHEAD + row * PSTR + sb2];
                acc.x += x.x; acc.y += x.y;
            }
            acc.x *= 0.125f; acc.y *= 0.125f;
            size_t oo = (size_t)b * T_DIM * S_DIM + (size_t)(t0 + row) * S_DIM + s0 + sb2;
            *(float2*)&avgw[oo] = acc;
        }
    }

    // ---- merge s-half partial PV accumulators, write attn_out ----
    __syncthreads();
    float* Os = Ps;
    if (sh == 1) {
#pragma unroll
        for (int mt = 0; mt < 2; mt++)
#pragma unroll
            for (int nd = 0; nd < 4; nd++)
#pragma unroll
                for (int r = 0; r < 4; r++)
                    Os[(h * 32 + lane) * 33 + mt * 16 + nd * 4 + r] = o[mt][nd][r];
    }
    __syncthreads();
    if (sh == 0) {
#pragma unroll
        for (int mt = 0; mt < 2; mt++) {
#pragma unroll
            for (int nd = 0; nd < 4; nd++) {
#pragma unroll
                for (int r = 0; r < 4; r++)
                    o[mt][nd][r] += Os[(h * 32 + lane) * 33 + mt * 16 + nd * 4 + r];
                int col = hb + nd * 8 + 2 * tig;
                size_t b0 = ((size_t)(t0 + mt * 16 + g)     * B_DIM + b) * E_DIM + col;
                size_t b1 = ((size_t)(t0 + mt * 16 + g + 8) * B_DIM + b) * E_DIM + col;
                *(float2*)&attn_out[b0] = make_float2(o[mt][nd][0], o[mt][nd][1]);
                *(float2*)&attn_out[b1] = make_float2(o[mt][nd][2], o[mt][nd][3]);
            }
        }
    }
}

// ---------------------------------------------------------------------------
extern "C" void kernel_launch(void* const* d_in, const int* in_sizes, int n_in,
                              void* d_out, int out_size)
{
    (void)in_sizes; (void)n_in; (void)out_size;

    const float* query = (const float*)d_in[0];
    const float* key   = (const float*)d_in[1];
    const float* value = (const float*)d_in[2];
    const float* Wq    = (const float*)d_in[3];
    const float* bq    = (const float*)d_in[4];
    const float* Wk    = (const float*)d_in[5];
    const float* bk    = (const float*)d_in[6];
    const float* Wo    = (const float*)d_in[7];
    const float* bo    = (const float*)d_in[8];

    float* out  = (float*)d_out;
    float* avgw = out + (size_t)T_DIM * B_DIM * E_DIM;

    float *qp = nullptr, *ao = nullptr;
    uint32_t *khi = nullptr, *klo = nullptr;
    cudaGetSymbolAddress((void**)&qp,  g_qproj);
    cudaGetSymbolAddress((void**)&khi, g_khi);
    cudaGetSymbolAddress((void**)&klo, g_klo);
    cudaGetSymbolAddress((void**)&ao,  g_attnout);

    const int rows_blocks = (T_DIM * B_DIM) / 32;   // 128
    const int pj_smem = PJ_FLOATS * 4;              // 92160

    cudaFuncSetAttribute(proj_qk_kernel, cudaFuncAttributeMaxDynamicSharedMemorySize, pj_smem);
    cudaFuncSetAttribute(proj_o_kernel,  cudaFuncAttributeMaxDynamicSharedMemorySize, pj_smem);

    proj_qk_kernel<<<dim3(rows_blocks, 2), 256, pj_smem>>>(query, Wq, bq, key, Wk, bk, qp, khi, klo);

    const int smem_bytes = SMEM_WORDS * 4;  // 172032
    cudaFuncSetAttribute(attn_tc_kernel, cudaFuncAttributeMaxDynamicSharedMemorySize, smem_bytes);
    attn_tc_kernel<<<dim3(T_DIM / 32, B_DIM), 512, smem_bytes>>>(value, avgw, ao);

    proj_o_kernel<<<rows_blocks, 256, pj_smem>>>(ao, Wo, bo, out);
}

// round 16
// speedup vs baseline: 1.1458x; 1.0447x over previous
#include <cuda_runtime.h>
#include <cstdint>

#define T_DIM 2048
#define S_DIM 2048
#define B_DIM 2
#define E_DIM 256
#define H_DIM 8
#define DH    32
#define SCLOG2E 0.25503511091247115f   // (1/sqrt(32)) * log2(e)

// Scratch (device globals: no allocation allowed in kernel_launch)
__device__ float    g_qproj[(size_t)T_DIM * B_DIM * E_DIM];
__device__ uint32_t g_khi[(size_t)S_DIM * B_DIM * (E_DIM / 2)];  // packed bf16x2 hi
__device__ uint32_t g_klo[(size_t)S_DIM * B_DIM * (E_DIM / 2)];  // packed bf16x2 lo
__device__ float    g_attnout[(size_t)T_DIM * B_DIM * E_DIM];

// ---------------- conversion helpers ----------------
__device__ __forceinline__ uint32_t f2tf32(float f) {
    uint32_t r; asm("cvt.rna.tf32.f32 %0, %1;" : "=r"(r) : "f"(f)); return r;
}
__device__ __forceinline__ float tf2f(uint32_t u) { return __uint_as_float(u); }
__device__ __forceinline__ float ex2f(float x) {
    float y; asm("ex2.approx.f32 %0, %1;" : "=f"(y) : "f"(x)); return y;
}
__device__ __forceinline__ uint32_t bfpack(float hi, float lo) {
    uint32_t r; asm("cvt.rn.bf16x2.f32 %0, %1, %2;" : "=r"(r) : "f"(hi), "f"(lo)); return r;
}
__device__ __forceinline__ float bflo_f(uint32_t u) { return __uint_as_float(u << 16); }
__device__ __forceinline__ float bfhi_f(uint32_t u) { return __uint_as_float(u & 0xffff0000u); }

__device__ __forceinline__ void mma_tf32(float* d, const uint32_t* a, const uint32_t* b) {
    asm volatile(
        "mma.sync.aligned.m16n8k8.row.col.f32.tf32.tf32.f32 "
        "{%0,%1,%2,%3}, {%4,%5,%6,%7}, {%8,%9}, {%0,%1,%2,%3};"
        : "+f"(d[0]), "+f"(d[1]), "+f"(d[2]), "+f"(d[3])
        : "r"(a[0]), "r"(a[1]), "r"(a[2]), "r"(a[3]), "r"(b[0]), "r"(b[1]));
}
__device__ __forceinline__ void mma_bf16(float* d, const uint32_t* a, const uint32_t* b) {
    asm volatile(
        "mma.sync.aligned.m16n8k16.row.col.f32.bf16.bf16.f32 "
        "{%0,%1,%2,%3}, {%4,%5,%6,%7}, {%8,%9}, {%0,%1,%2,%3};"
        : "+f"(d[0]), "+f"(d[1]), "+f"(d[2]), "+f"(d[3])
        : "r"(a[0]), "r"(a[1]), "r"(a[2]), "r"(a[3]), "r"(b[0]), "r"(b[1]));
}

// ---------------- cp.async helpers (.ca — measured best) ----------------
__device__ __forceinline__ void cpa16(uint32_t s, const void* g) {
    asm volatile("cp.async.ca.shared.global [%0], [%1], 16;" :: "r"(s), "l"(g) : "memory");
}
#define CP_COMMIT() asm volatile("cp.async.commit_group;" ::: "memory")
#define CP_WAIT0()  asm volatile("cp.async.wait_group 0;" ::: "memory")

// attn smem layout (words)
#define KWSTR 132
#define VSTR  264
#define PSTR  36
#define PHEAD (32 * PSTR)
#define KH_OFF 0
#define KL_OFF (2 * 32 * KWSTR)            //  8448
#define V_OFF  (4 * 32 * KWSTR)            // 16896
#define PS_OFF (V_OFF + 2 * 32 * VSTR)     // 33792
#define SMEM_WORDS (PS_OFF + 8 * 32 * PSTR) // 43008 -> 172032 B
#define P1STAGE (128 * KWSTR)              // 16896 (pass1 Kh stages fill [0,PS_OFF))

// proj smem layout (floats): Ws[2][256*36] | Xh[2][32*36] | Xl[2][32*36]
#define PJ_WSZ   (256 * 36)
#define PJ_XSZ   (32 * 36)
#define PJ_XH0   (2 * PJ_WSZ)
#define PJ_XL0   (2 * PJ_WSZ + 2 * PJ_XSZ)
#define PJ_FLOATS (2 * PJ_WSZ + 4 * PJ_XSZ) // 23040 -> 92160 B

// ---------------------------------------------------------------------------
// proj body: 3xTF32, 32 rows x 256 cols per block, W split in-kernel,
// 2-stage cp.async pipeline (R11 measured-best version).
// ---------------------------------------------------------------------------
__device__ __forceinline__ void proj_tc_body(
    const float* __restrict__ X, const float* __restrict__ W,
    const float* __restrict__ bias, float* __restrict__ Y,
    uint32_t* __restrict__ khi, uint32_t* __restrict__ klo,
    int add_residual, int r0)
{
    extern __shared__ float pj[];
    const uint32_t sbase = (uint32_t)__cvta_generic_to_shared(pj);

    const int tid  = threadIdx.x;
    const int w    = tid >> 5;
    const int lane = tid & 31;
    const int g    = lane >> 2;
    const int tig  = lane & 3;

    float d[2][4][4];
#pragma unroll
    for (int mt = 0; mt < 2; mt++)
#pragma unroll
        for (int nt = 0; nt < 4; nt++)
#pragma unroll
            for (int r = 0; r < 4; r++) d[mt][nt][r] = 0.f;

    float xv[4];
#pragma unroll
    for (int i = 0; i < 8; i++) {
        int idx = tid + i * 256;
        int n = idx >> 3, c4 = (idx & 7) * 4;
        cpa16(sbase + (uint32_t)(n * 36 + c4) * 4, &W[(size_t)n * E_DIM + c4]);
    }
    CP_COMMIT();
#pragma unroll
    for (int i = 0; i < 4; i++) {
        int idx = tid + i * 256;
        int r = idx >> 5, e = idx & 31;
        xv[i] = X[(size_t)(r0 + r) * E_DIM + e];
    }

    for (int c = 0; c < 8; c++) {
        const int st = c & 1;
        float* Ws = pj + st * PJ_WSZ;
        float* Xh = pj + PJ_XH0 + st * PJ_XSZ;
        float* Xl = pj + PJ_XL0 + st * PJ_XSZ;

#pragma unroll
        for (int i = 0; i < 4; i++) {
            int idx = tid + i * 256;
            int r = idx >> 5, e = idx & 31;
            float hh = tf2f(f2tf32(xv[i]));
            Xh[r * 36 + e] = hh;
            Xl[r * 36 + e] = xv[i] - hh;
        }
        CP_WAIT0();
        __syncthreads();

        if (c + 1 < 8) {
            int e0n = (c + 1) * 32;
            uint32_t dst = sbase + (uint32_t)((st ^ 1) * PJ_WSZ) * 4;
#pragma unroll
            for (int i = 0; i < 8; i++) {
                int idx = tid + i * 256;
                int n = idx >> 3, c4 = (idx & 7) * 4;
                cpa16(dst + (uint32_t)(n * 36 + c4) * 4, &W[(size_t)n * E_DIM + e0n + c4]);
            }
            CP_COMMIT();
#pragma unroll
            for (int i = 0; i < 4; i++) {
                int idx = tid + i * 256;
                int r = idx >> 5, e = idx & 31;
                xv[i] = X[(size_t)(r0 + r) * E_DIM + e0n + e];
            }
        }

#pragma unroll
        for (int k8 = 0; k8 < 4; k8++) {
            uint32_t ah[2][4], al[2][4];
#pragma unroll
            for (int mt = 0; mt < 2; mt++) {
                int rA = mt * 16 + g;
                ah[mt][0] = __float_as_uint(Xh[rA * 36 + k8 * 8 + tig]);
                ah[mt][1] = __float_as_uint(Xh[(rA + 8) * 36 + k8 * 8 + tig]);
                ah[mt][2] = __float_as_uint(Xh[rA * 36 + k8 * 8 + tig + 4]);
                ah[mt][3] = __float_as_uint(Xh[(rA + 8) * 36 + k8 * 8 + tig + 4]);
                al[mt][0] = f2tf32(Xl[rA * 36 + k8 * 8 + tig]);
                al[mt][1] = f2tf32(Xl[(rA + 8) * 36 + k8 * 8 + tig]);
                al[mt][2] = f2tf32(Xl[rA * 36 + k8 * 8 + tig + 4]);
                al[mt][3] = f2tf32(Xl[(rA + 8) * 36 + k8 * 8 + tig + 4]);
            }
#pragma unroll
            for (int nt = 0; nt < 4; nt++) {
                int n = w * 32 + nt * 8 + g;
                float w0 = Ws[n * 36 + k8 * 8 + tig], w1 = Ws[n * 36 + k8 * 8 + tig + 4];
                uint32_t bh[2], bl[2];
                bh[0] = f2tf32(w0); bl[0] = f2tf32(w0 - tf2f(bh[0]));
                bh[1] = f2tf32(w1); bl[1] = f2tf32(w1 - tf2f(bh[1]));
                mma_tf32(d[0][nt], ah[0], bh);
                mma_tf32(d[1][nt], ah[1], bh);
                mma_tf32(d[0][nt], al[0], bh);
                mma_tf32(d[1][nt], al[1], bh);
                mma_tf32(d[0][nt], ah[0], bl);
                mma_tf32(d[1][nt], ah[1], bl);
            }
        }
    }

#pragma unroll
    for (int mt = 0; mt < 2; mt++) {
#pragma unroll
        for (int nt = 0; nt < 4; nt++) {
            int c = w * 32 + nt * 8 + 2 * tig;
            float b0 = __ldg(&bias[c]), b1 = __ldg(&bias[c + 1]);
            int ra = r0 + mt * 16 + g;
            int rb2 = ra + 8;
            float y0 = d[mt][nt][0] + b0, y1 = d[mt][nt][1] + b1;
            float y2 = d[mt][nt][2] + b0, y3 = d[mt][nt][3] + b1;
            if (khi) {
                uint32_t hi0 = bfpack(y1, y0);
                uint32_t lo0 = bfpack(y1 - bfhi_f(hi0), y0 - bflo_f(hi0));
                uint32_t hi1 = bfpack(y3, y2);
                uint32_t lo1 = bfpack(y3 - bfhi_f(hi1), y2 - bflo_f(hi1));
                khi[(size_t)ra  * 128 + (c >> 1)] = hi0;
                klo[(size_t)ra  * 128 + (c >> 1)] = lo0;
                khi[(size_t)rb2 * 128 + (c >> 1)] = hi1;
                klo[(size_t)rb2 * 128 + (c >> 1)] = lo1;
            } else {
                size_t o0 = (size_t)ra  * E_DIM + c;
                size_t o1 = (size_t)rb2 * E_DIM + c;
                if (add_residual) {
                    float2 x0 = *(const float2*)&X[o0];
                    float2 x1 = *(const float2*)&X[o1];
                    y0 += x0.x; y1 += x0.y; y2 += x1.x; y3 += x1.y;
                }
                *(float2*)&Y[o0] = make_float2(y0, y1);
                *(float2*)&Y[o1] = make_float2(y2, y3);
            }
        }
    }
}

__global__ __launch_bounds__(256, 2) void proj_qk_kernel(
    const float* __restrict__ Xq, const float* __restrict__ Wq, const float* __restrict__ bq,
    const float* __restrict__ Xk, const float* __restrict__ Wk, const float* __restrict__ bk,
    float* __restrict__ Yq, uint32_t* __restrict__ khi, uint32_t* __restrict__ klo)
{
    int r0 = blockIdx.x * 32;
    if (blockIdx.y == 0) proj_tc_body(Xq, Wq, bq, Yq, nullptr, nullptr, 0, r0);
    else                 proj_tc_body(Xk, Wk, bk, nullptr, khi, klo, 0, r0);
}

__global__ __launch_bounds__(256, 2) void proj_o_kernel(
    const float* __restrict__ X, const float* __restrict__ W,
    const float* __restrict__ bias, float* __restrict__ Y)
{
    proj_tc_body(X, W, bias, Y, nullptr, nullptr, 1, blockIdx.x * 32);
}

// ---------------------------------------------------------------------------
// attn_tc_kernel: R11 loop structure; K fragment gathers via ldmatrix.x4
// (same bits into same registers — 4x fewer shared-load instructions).
// ---------------------------------------------------------------------------
__global__ __launch_bounds__(512, 1) void attn_tc_kernel(
    const float* __restrict__ value,
    float* __restrict__ avgw,
    float* __restrict__ attn_out)
{
    extern __shared__ uint32_t smu[];
    float* Ps = (float*)(smu + PS_OFF);
    __shared__ float Lsh[16][32][4];

    const uint32_t sb = (uint32_t)__cvta_generic_to_shared(smu);

    const int tid  = threadIdx.x;
    const int wid  = tid >> 5;
    const int h    = wid & 7;
    const int sh   = wid >> 3;
    const int lane = tid & 31;
    const int g    = lane >> 2;
    const int tig  = lane & 3;
    const int r8   = lane & 7;         // ldmatrix row within 8-row group
    const int quad = lane >> 3;        // ldmatrix matrix selector (0..3)
    const int t0   = blockIdx.x * 32;
    const int b    = blockIdx.y;
    const int hb   = h * DH;
    const int hw   = hb >> 1;

    // ---- Q fragments: bf16 2-split ----
    uint32_t qh[2][2][4], ql[2][2][4];
#pragma unroll
    for (int mt = 0; mt < 2; mt++) {
#pragma unroll
        for (int jc = 0; jc < 2; jc++) {
            int r = t0 + mt * 16 + g;
            int c = hb + jc * 16 + 2 * tig;
            float2 v0 = *(const float2*)&g_qproj[((size_t)r       * B_DIM + b) * E_DIM + c];
            float2 v1 = *(const float2*)&g_qproj[((size_t)(r + 8) * B_DIM + b) * E_DIM + c];
            float2 v2 = *(const float2*)&g_qproj[((size_t)r       * B_DIM + b) * E_DIM + c + 8];
            float2 v3 = *(const float2*)&g_qproj[((size_t)(r + 8) * B_DIM + b) * E_DIM + c + 8];
            qh[mt][jc][0] = bfpack(v0.y, v0.x);
            qh[mt][jc][1] = bfpack(v1.y, v1.x);
            qh[mt][jc][2] = bfpack(v2.y, v2.x);
            qh[mt][jc][3] = bfpack(v3.y, v3.x);
            ql[mt][jc][0] = bfpack(v0.y - bfhi_f(qh[mt][jc][0]), v0.x - bflo_f(qh[mt][jc][0]));
            ql[mt][jc][1] = bfpack(v1.y - bfhi_f(qh[mt][jc][1]), v1.x - bflo_f(qh[mt][jc][1]));
            ql[mt][jc][2] = bfpack(v2.y - bfhi_f(qh[mt][jc][2]), v2.x - bflo_f(qh[mt][jc][2]));
            ql[mt][jc][3] = bfpack(v3.y - bfhi_f(qh[mt][jc][3]), v3.x - bflo_f(qh[mt][jc][3]));
        }
    }

    // ========= pass 1: lsum via 1-term bf16 QK, 128-row tiles =========
    float lsum[4] = {0.f, 0.f, 0.f, 0.f};
    {
        const int NT1 = S_DIM / 128;          // 16

#pragma unroll
        for (int i = 0; i < 8; i++) {
            int idx = tid + i * 512;
            int row = idx >> 5, c = idx & 31;
            cpa16(sb + (uint32_t)(row * KWSTR + c * 4) * 4,
                  &g_khi[((size_t)row * B_DIM + b) * 128 + c * 4]);
        }
        CP_COMMIT();

        for (int t = 0; t < NT1; t++) {
            CP_WAIT0();
            __syncthreads();
            if (t + 1 < NT1) {
                int s0n = (t + 1) * 128;
                uint32_t dst = sb + (uint32_t)(((t + 1) & 1) * P1STAGE) * 4;
#pragma unroll
                for (int i = 0; i < 8; i++) {
                    int idx = tid + i * 512;
                    int row = idx >> 5, c = idx & 31;
                    cpa16(dst + (uint32_t)(row * KWSTR + c * 4) * 4,
                          &g_khi[((size_t)(s0n + row) * B_DIM + b) * 128 + c * 4]);
                }
            }
            CP_COMMIT();

            const uint32_t stage_w = (uint32_t)((t & 1) * P1STAGE);

#pragma unroll
            for (int sub = 0; sub < 2; sub++) {
                const int soW1 = sub * 64 + sh * 32;
                float d[2][4][4];
#pragma unroll
                for (int mt = 0; mt < 2; mt++)
#pragma unroll
                    for (int nt = 0; nt < 4; nt++)
#pragma unroll
                        for (int r = 0; r < 4; r++) d[mt][nt][r] = 0.f;

#pragma unroll
                for (int jc = 0; jc < 2; jc++) {
                    uint32_t bh[4][2];
#pragma unroll
                    for (int np = 0; np < 2; np++) {
                        // x4: M0/M1 = nt0 words 0/+4, M2/M3 = nt0+1 words 0/+4
                        int nt0 = np * 2;
                        int woff = (soW1 + (nt0 + (quad >> 1)) * 8 + r8) * KWSTR
                                 + hw + jc * 8 + (quad & 1) * 4;
                        uint32_t addr = sb + (stage_w + (uint32_t)woff) * 4;
                        asm volatile(
                            "ldmatrix.sync.aligned.m8n8.x4.shared.b16 {%0,%1,%2,%3}, [%4];"
                            : "=r"(bh[nt0][0]), "=r"(bh[nt0][1]),
                              "=r"(bh[nt0 + 1][0]), "=r"(bh[nt0 + 1][1])
                            : "r"(addr));
                    }
#pragma unroll
                    for (int nt = 0; nt < 4; nt++) {
                        mma_bf16(d[0][nt], qh[0][jc], bh[nt]);
                        mma_bf16(d[1][nt], qh[1][jc], bh[nt]);
                    }
                }
#pragma unroll
                for (int mt = 0; mt < 2; mt++)
#pragma unroll
                    for (int nt = 0; nt < 4; nt++)
#pragma unroll
                        for (int r = 0; r < 4; r++)
                            lsum[mt * 2 + (r >> 1)] += ex2f(d[mt][nt][r] * SCLOG2E);
            }
        }
    }
#pragma unroll
    for (int r = 0; r < 4; r++) {
        lsum[r] += __shfl_xor_sync(0xffffffffu, lsum[r], 1);
        lsum[r] += __shfl_xor_sync(0xffffffffu, lsum[r], 2);
    }
#pragma unroll
    for (int r = 0; r < 4; r++) Lsh[wid][lane][r] = lsum[r];
    __syncthreads();
    float inv[4];
#pragma unroll
    for (int r = 0; r < 4; r++) inv[r] = 1.0f / (lsum[r] + Lsh[wid ^ 8][lane][r]);

    // ================= pass 2 =================
    float o[2][4][4];
#pragma unroll
    for (int mt = 0; mt < 2; mt++)
#pragma unroll
        for (int nd = 0; nd < 4; nd++)
#pragma unroll
            for (int r = 0; r < 4; r++) o[mt][nd][r] = 0.f;

    const int soW = sh * 16;
    const int NT = S_DIM / 32;

    {
        uint32_t dkh = sb + (uint32_t)(KH_OFF) * 4;
        uint32_t dkl = sb + (uint32_t)(KL_OFF) * 4;
        uint32_t dv  = sb + (uint32_t)(V_OFF) * 4;
#pragma unroll
        for (int i = 0; i < 2; i++) {
            int idx = tid + i * 512;
            int row = idx >> 5, c = idx & 31;
            size_t gsrc = ((size_t)row * B_DIM + b) * 128 + c * 4;
            cpa16(dkh + (uint32_t)(row * KWSTR + c * 4) * 4, &g_khi[gsrc]);
            cpa16(dkl + (uint32_t)(row * KWSTR + c * 4) * 4, &g_klo[gsrc]);
        }
#pragma unroll
        for (int i = 0; i < 4; i++) {
            int idx = tid + i * 512;
            int row = idx >> 6, c = idx & 63;
            cpa16(dv + (uint32_t)(row * VSTR + c * 4) * 4,
                  &value[((size_t)row * B_DIM + b) * 256 + c * 4]);
        }
    }
    CP_COMMIT();

    for (int t = 0; t < NT; t++) {
        CP_WAIT0();
        __syncthreads();
        if (t + 1 < NT) {
            int nst = (t + 1) & 1;
            int s0n = (t + 1) * 32;
            uint32_t dkh = sb + (uint32_t)(KH_OFF + nst * 32 * KWSTR) * 4;
            uint32_t dkl = sb + (uint32_t)(KL_OFF + nst * 32 * KWSTR) * 4;
            uint32_t dv  = sb + (uint32_t)(V_OFF  + nst * 32 * VSTR) * 4;
#pragma unroll
            for (int i = 0; i < 2; i++) {
                int idx = tid + i * 512;
                int row = idx >> 5, c = idx & 31;
                size_t gsrc = ((size_t)(s0n + row) * B_DIM + b) * 128 + c * 4;
                cpa16(dkh + (uint32_t)(row * KWSTR + c * 4) * 4, &g_khi[gsrc]);
                cpa16(dkl + (uint32_t)(row * KWSTR + c * 4) * 4, &g_klo[gsrc]);
            }
#pragma unroll
            for (int i = 0; i < 4; i++) {
                int idx = tid + i * 512;
                int row = idx >> 6, c = idx & 63;
                cpa16(dv + (uint32_t)(row * VSTR + c * 4) * 4,
                      &value[((size_t)(s0n + row) * B_DIM + b) * 256 + c * 4]);
            }
        }
        CP_COMMIT();

        const int st = t & 1;
        const float* Vs = (const float*)(smu + V_OFF + st * 32 * VSTR);
        const uint32_t stage_w = (uint32_t)(KH_OFF + st * 32 * KWSTR);
        const int s0 = t * 32;

        float d[2][2][4];
#pragma unroll
        for (int mt = 0; mt < 2; mt++)
#pragma unroll
            for (int nt = 0; nt < 2; nt++)
#pragma unroll
                for (int r = 0; r < 4; r++) d[mt][nt][r] = 0.f;

#pragma unroll
        for (int jc = 0; jc < 2; jc++) {
            uint32_t bh[2][2], bl[2][2];
#pragma unroll
            for (int nt = 0; nt < 2; nt++) {
                // x4: M0/M1 = Kh words 0/+4, M2/M3 = Kl words 0/+4
                int woff = (soW + nt * 8 + r8) * KWSTR + hw + jc * 8
                         + (quad & 1) * 4 + (quad >> 1) * (KL_OFF - KH_OFF);
                uint32_t addr = sb + (stage_w + (uint32_t)woff) * 4;
                asm volatile(
                    "ldmatrix.sync.aligned.m8n8.x4.shared.b16 {%0,%1,%2,%3}, [%4];"
                    : "=r"(bh[nt][0]), "=r"(bh[nt][1]), "=r"(bl[nt][0]), "=r"(bl[nt][1])
                    : "r"(addr));
            }
#pragma unroll
            for (int nt = 0; nt < 2; nt++) {
                mma_bf16(d[0][nt], qh[0][jc], bh[nt]);
                mma_bf16(d[1][nt], qh[1][jc], bh[nt]);
            }
#pragma unroll
            for (int nt = 0; nt < 2; nt++) {
                mma_bf16(d[0][nt], ql[0][jc], bh[nt]);
                mma_bf16(d[1][nt], ql[1][jc], bh[nt]);
            }
#pragma unroll
            for (int nt = 0; nt < 2; nt++) {
                mma_bf16(d[0][nt], qh[0][jc], bl[nt]);
                mma_bf16(d[1][nt], qh[1][jc], bl[nt]);
            }
        }

        // normalize, stage p into Ps
#pragma unroll
        for (int mt = 0; mt < 2; mt++) {
#pragma unroll
            for (int nt = 0; nt < 2; nt++) {
                float p0 = ex2f(d[mt][nt][0] * SCLOG2E) * inv[mt * 2 + 0];
                float p1 = ex2f(d[mt][nt][1] * SCLOG2E) * inv[mt * 2 + 0];
                float p2 = ex2f(d[mt][nt][2] * SCLOG2E) * inv[mt * 2 + 1];
                float p3 = ex2f(d[mt][nt][3] * SCLOG2E) * inv[mt * 2 + 1];
                int scol = soW + nt * 8 + 2 * tig;
                *(float2*)&Ps[h * PHEAD + (mt * 16 + g)     * PSTR + scol] = make_float2(p0, p1);
                *(float2*)&Ps[h * PHEAD + (mt * 16 + g + 8) * PSTR + scol] = make_float2(p2, p3);
            }
        }
        __syncwarp();

        // PV over this warp's 16 s-rows: 1xTF32
#pragma unroll
        for (int ks = 0; ks < 2; ks++) {
            uint32_t a[2][4];
            int sc = soW + ks * 8 + tig;
#pragma unroll
            for (int mt = 0; mt < 2; mt++) {
                int rb = mt * 16;
                a[mt][0] = f2tf32(Ps[h * PHEAD + (rb + g)     * PSTR + sc]);
                a[mt][1] = f2tf32(Ps[h * PHEAD + (rb + g + 8) * PSTR + sc]);
                a[mt][2] = f2tf32(Ps[h * PHEAD + (rb + g)     * PSTR + sc + 4]);
                a[mt][3] = f2tf32(Ps[h * PHEAD + (rb + g + 8) * PSTR + sc + 4]);
            }
#pragma unroll
            for (int nd = 0; nd < 4; nd++) {
                uint32_t bb[2];
                bb[0] = f2tf32(Vs[(soW + ks * 8 + tig)     * VSTR + hb + nd * 8 + g]);
                bb[1] = f2tf32(Vs[(soW + ks * 8 + tig + 4) * VSTR + hb + nd * 8 + g]);
                mma_tf32(o[0][nd], a[0], bb);
                mma_tf32(o[1][nd], a[1], bb);
            }
        }
        __syncthreads();

        // avg_weights tile [32 t x 32 s]
        {
            int row = tid >> 4;
            int sb2 = (tid & 15) * 2;
            float2 acc = make_float2(0.f, 0.f);
#pragma unroll
            for (int hh = 0; hh < 8; hh++) {
                float2 x = *(const float2*)&Ps[hh * PHEAD + row * PSTR + sb2];
                acc.x += x.x; acc.y += x.y;
            }
            acc.x *= 0.125f; acc.y *= 0.125f;
            size_t oo = (size_t)b * T_DIM * S_DIM + (size_t)(t0 + row) * S_DIM + s0 + sb2;
            *(float2*)&avgw[oo] = acc;
        }
    }

    // ---- merge s-half partial PV accumulators, write attn_out ----
    __syncthreads();
    float* Os = Ps;
    if (sh == 1) {
#pragma unroll
        for (int mt = 0; mt < 2; mt++)
#pragma unroll
            for (int nd = 0; nd < 4; nd++)
#pragma unroll
                for (int r = 0; r < 4; r++)
                    Os[(h * 32 + lane) * 33 + mt * 16 + nd * 4 + r] = o[mt][nd][r];
    }
    __syncthreads();
    if (sh == 0) {
#pragma unroll
        for (int mt = 0; mt < 2; mt++) {
#pragma unroll
            for (int nd = 0; nd < 4; nd++) {
#pragma unroll
                for (int r = 0; r < 4; r++)
                    o[mt][nd][r] += Os[(h * 32 + lane) * 33 + mt * 16 + nd * 4 + r];
                int col = hb + nd * 8 + 2 * tig;
                size_t b0 = ((size_t)(t0 + mt * 16 + g)     * B_DIM + b) * E_DIM + col;
                size_t b1 = ((size_t)(t0 + mt * 16 + g + 8) * B_DIM + b) * E_DIM + col;
                *(float2*)&attn_out[b0] = make_float2(o[mt][nd][0], o[mt][nd][1]);
                *(float2*)&attn_out[b1] = make_float2(o[mt][nd][2], o[mt][nd][3]);
            }
        }
    }
}

// ---------------------------------------------------------------------------
extern "C" void kernel_launch(void* const* d_in, const int* in_sizes, int n_in,
                              void* d_out, int out_size)
{
    (void)in_sizes; (void)n_in; (void)out_size;

    const float* query = (const float*)d_in[0];
    const float* key   = (const float*)d_in[1];
    const float* value = (const float*)d_in[2];
    const float* Wq    = (const float*)d_in[3];
    const float* bq    = (const float*)d_in[4];
    const float* Wk    = (const float*)d_in[5];
    const float* bk    = (const float*)d_in[6];
    const float* Wo    = (const float*)d_in[7];
    const float* bo    = (const float*)d_in[8];

    float* out  = (float*)d_out;
    float* avgw = out + (size_t)T_DIM * B_DIM * E_DIM;

    float *qp = nullptr, *ao = nullptr;
    uint32_t *khi = nullptr, *klo = nullptr;
    cudaGetSymbolAddress((void**)&qp,  g_qproj);
    cudaGetSymbolAddress((void**)&khi, g_khi);
    cudaGetSymbolAddress((void**)&klo, g_klo);
    cudaGetSymbolAddress((void**)&ao,  g_attnout);

    const int rows_blocks = (T_DIM * B_DIM) / 32;   // 128
    const int pj_smem = PJ_FLOATS * 4;              // 92160

    cudaFuncSetAttribute(proj_qk_kernel, cudaFuncAttributeMaxDynamicSharedMemorySize, pj_smem);
    cudaFuncSetAttribute(proj_o_kernel,  cudaFuncAttributeMaxDynamicSharedMemorySize, pj_smem);

    proj_qk_kernel<<<dim3(rows_blocks, 2), 256, pj_smem>>>(query, Wq, bq, key, Wk, bk, qp, khi, klo);

    const int smem_bytes = SMEM_WORDS * 4;  // 172032
    cudaFuncSetAttribute(attn_tc_kernel, cudaFuncAttributeMaxDynamicSharedMemorySize, smem_bytes);
    attn_tc_kernel<<<dim3(T_DIM / 32, B_DIM), 512, smem_bytes>>>(value, avgw, ao);

    proj_o_kernel<<<rows_blocks, 256, pj_smem>>>(ao, Wo, bo, out);
}

// round 17
// speedup vs baseline: 1.1721x; 1.0230x over previous
#include <cuda_runtime.h>
#include <cstdint>

#define T_DIM 2048
#define S_DIM 2048
#define B_DIM 2
#define E_DIM 256
#define H_DIM 8
#define DH    32
#define SCLOG2E 0.25503511091247115f   // (1/sqrt(32)) * log2(e)

// Scratch (device globals: no allocation allowed in kernel_launch)
__device__ float    g_qproj[(size_t)T_DIM * B_DIM * E_DIM];
__device__ uint32_t g_khi[(size_t)S_DIM * B_DIM * (E_DIM / 2)];  // packed bf16x2 hi
__device__ uint32_t g_klo[(size_t)S_DIM * B_DIM * (E_DIM / 2)];  // packed bf16x2 lo
__device__ float    g_attnout[(size_t)T_DIM * B_DIM * E_DIM];

// ---------------- conversion helpers ----------------
__device__ __forceinline__ uint32_t f2tf32(float f) {
    uint32_t r; asm("cvt.rna.tf32.f32 %0, %1;" : "=r"(r) : "f"(f)); return r;
}
__device__ __forceinline__ float tf2f(uint32_t u) { return __uint_as_float(u); }
__device__ __forceinline__ float ex2f(float x) {
    float y; asm("ex2.approx.f32 %0, %1;" : "=f"(y) : "f"(x)); return y;
}
__device__ __forceinline__ uint32_t bfpack(float hi, float lo) {
    uint32_t r; asm("cvt.rn.bf16x2.f32 %0, %1, %2;" : "=r"(r) : "f"(hi), "f"(lo)); return r;
}
__device__ __forceinline__ float bflo_f(uint32_t u) { return __uint_as_float(u << 16); }
__device__ __forceinline__ float bfhi_f(uint32_t u) { return __uint_as_float(u & 0xffff0000u); }

__device__ __forceinline__ void mma_tf32(float* d, const uint32_t* a, const uint32_t* b) {
    asm volatile(
        "mma.sync.aligned.m16n8k8.row.col.f32.tf32.tf32.f32 "
        "{%0,%1,%2,%3}, {%4,%5,%6,%7}, {%8,%9}, {%0,%1,%2,%3};"
        : "+f"(d[0]), "+f"(d[1]), "+f"(d[2]), "+f"(d[3])
        : "r"(a[0]), "r"(a[1]), "r"(a[2]), "r"(a[3]), "r"(b[0]), "r"(b[1]));
}
__device__ __forceinline__ void mma_bf16(float* d, const uint32_t* a, const uint32_t* b) {
    asm volatile(
        "mma.sync.aligned.m16n8k16.row.col.f32.bf16.bf16.f32 "
        "{%0,%1,%2,%3}, {%4,%5,%6,%7}, {%8,%9}, {%0,%1,%2,%3};"
        : "+f"(d[0]), "+f"(d[1]), "+f"(d[2]), "+f"(d[3])
        : "r"(a[0]), "r"(a[1]), "r"(a[2]), "r"(a[3]), "r"(b[0]), "r"(b[1]));
}

// ---------------- cp.async helpers (.ca — measured best) ----------------
__device__ __forceinline__ void cpa16(uint32_t s, const void* g) {
    asm volatile("cp.async.ca.shared.global [%0], [%1], 16;" :: "r"(s), "l"(g) : "memory");
}
#define CP_COMMIT() asm volatile("cp.async.commit_group;" ::: "memory")
#define CP_WAIT0()  asm volatile("cp.async.wait_group 0;" ::: "memory")

// attn smem layout (words)
#define KWSTR 132
#define VSTR  264
#define PSTR  36
#define PHEAD (32 * PSTR)
#define KH_OFF 0
#define KL_OFF (2 * 32 * KWSTR)            //  8448
#define V_OFF  (4 * 32 * KWSTR)            // 16896
#define PS_OFF (V_OFF + 2 * 32 * VSTR)     // 33792
#define SMEM_WORDS (PS_OFF + 8 * 32 * PSTR) // 43008 -> 172032 B
#define P1STAGE (128 * KWSTR)              // 16896 (pass1 Kh stages fill [0,PS_OFF))

// proj smem layout (floats): Ws[2][256*36] | Xh[2][32*36] | Xl[2][32*36]
#define PJ_WSZ   (256 * 36)
#define PJ_XSZ   (32 * 36)
#define PJ_XH0   (2 * PJ_WSZ)
#define PJ_XL0   (2 * PJ_WSZ + 2 * PJ_XSZ)
#define PJ_FLOATS (2 * PJ_WSZ + 4 * PJ_XSZ) // 23040 -> 92160 B

// ---------------------------------------------------------------------------
// proj body: 3xTF32, 32 rows x 256 cols per block, W split in-kernel,
// 2-stage cp.async pipeline; fragment gathers via ldmatrix.x4 (bit-identical).
// ---------------------------------------------------------------------------
__device__ __forceinline__ void proj_tc_body(
    const float* __restrict__ X, const float* __restrict__ W,
    const float* __restrict__ bias, float* __restrict__ Y,
    uint32_t* __restrict__ khi, uint32_t* __restrict__ klo,
    int add_residual, int r0)
{
    extern __shared__ float pj[];
    const uint32_t sbase = (uint32_t)__cvta_generic_to_shared(pj);

    const int tid  = threadIdx.x;
    const int w    = tid >> 5;
    const int lane = tid & 31;
    const int g    = lane >> 2;
    const int tig  = lane & 3;
    const int r8   = lane & 7;
    const int quad = lane >> 3;

    float d[2][4][4];
#pragma unroll
    for (int mt = 0; mt < 2; mt++)
#pragma unroll
        for (int nt = 0; nt < 4; nt++)
#pragma unroll
            for (int r = 0; r < 4; r++) d[mt][nt][r] = 0.f;

    float xv[4];
#pragma unroll
    for (int i = 0; i < 8; i++) {
        int idx = tid + i * 256;
        int n = idx >> 3, c4 = (idx & 7) * 4;
        cpa16(sbase + (uint32_t)(n * 36 + c4) * 4, &W[(size_t)n * E_DIM + c4]);
    }
    CP_COMMIT();
#pragma unroll
    for (int i = 0; i < 4; i++) {
        int idx = tid + i * 256;
        int r = idx >> 5, e = idx & 31;
        xv[i] = X[(size_t)(r0 + r) * E_DIM + e];
    }

    for (int c = 0; c < 8; c++) {
        const int st = c & 1;
        const int WS_base = st * PJ_WSZ;
        const int XH_base = PJ_XH0 + st * PJ_XSZ;
        const int XL_base = PJ_XL0 + st * PJ_XSZ;
        float* Xh = pj + XH_base;
        float* Xl = pj + XL_base;

#pragma unroll
        for (int i = 0; i < 4; i++) {
            int idx = tid + i * 256;
            int r = idx >> 5, e = idx & 31;
            float hh = tf2f(f2tf32(xv[i]));
            Xh[r * 36 + e] = hh;
            Xl[r * 36 + e] = xv[i] - hh;
        }
        CP_WAIT0();
        __syncthreads();

        if (c + 1 < 8) {
            int e0n = (c + 1) * 32;
            uint32_t dst = sbase + (uint32_t)((st ^ 1) * PJ_WSZ) * 4;
#pragma unroll
            for (int i = 0; i < 8; i++) {
                int idx = tid + i * 256;
                int n = idx >> 3, c4 = (idx & 7) * 4;
                cpa16(dst + (uint32_t)(n * 36 + c4) * 4, &W[(size_t)n * E_DIM + e0n + c4]);
            }
            CP_COMMIT();
#pragma unroll
            for (int i = 0; i < 4; i++) {
                int idx = tid + i * 256;
                int r = idx >> 5, e = idx & 31;
                xv[i] = X[(size_t)(r0 + r) * E_DIM + e0n + e];
            }
        }

        // ldmatrix row/word selectors (32-bit elements viewed as b16 tiles)
        const int xrow  = (quad & 1) * 8 + r8;      // row within 16-row A block
        const int xwsel = (quad >> 1) * 4;          // word half (0 / +4)

#pragma unroll
        for (int k8 = 0; k8 < 4; k8++) {
            uint32_t ah[2][4], al[2][4];
#pragma unroll
            for (int mt = 0; mt < 2; mt++) {
                uint32_t addrh = sbase + (uint32_t)(XH_base +
                    (mt * 16 + xrow) * 36 + k8 * 8 + xwsel) * 4;
                asm volatile(
                    "ldmatrix.sync.aligned.m8n8.x4.shared.b16 {%0,%1,%2,%3}, [%4];"
                    : "=r"(ah[mt][0]), "=r"(ah[mt][1]), "=r"(ah[mt][2]), "=r"(ah[mt][3])
                    : "r"(addrh));
                uint32_t addrl = sbase + (uint32_t)(XL_base +
                    (mt * 16 + xrow) * 36 + k8 * 8 + xwsel) * 4;
                uint32_t rl[4];
                asm volatile(
                    "ldmatrix.sync.aligned.m8n8.x4.shared.b16 {%0,%1,%2,%3}, [%4];"
                    : "=r"(rl[0]), "=r"(rl[1]), "=r"(rl[2]), "=r"(rl[3])
                    : "r"(addrl));
                al[mt][0] = f2tf32(__uint_as_float(rl[0]));
                al[mt][1] = f2tf32(__uint_as_float(rl[1]));
                al[mt][2] = f2tf32(__uint_as_float(rl[2]));
                al[mt][3] = f2tf32(__uint_as_float(rl[3]));
            }

            // W fragments: 2 ldmatrix.x4 cover 4 nt (quads = {nt-pair, word-half})
            uint32_t wv[2][4];
#pragma unroll
            for (int np = 0; np < 2; np++) {
                int nrow = w * 32 + (np * 2 + (quad >> 1)) * 8 + r8;
                uint32_t addrw = sbase + (uint32_t)(WS_base +
                    nrow * 36 + k8 * 8 + (quad & 1) * 4) * 4;
                asm volatile(
                    "ldmatrix.sync.aligned.m8n8.x4.shared.b16 {%0,%1,%2,%3}, [%4];"
                    : "=r"(wv[np][0]), "=r"(wv[np][1]), "=r"(wv[np][2]), "=r"(wv[np][3])
                    : "r"(addrw));
            }
#pragma unroll
            for (int nt = 0; nt < 4; nt++) {
                float w0 = __uint_as_float(wv[nt >> 1][(nt & 1) * 2]);
                float w1 = __uint_as_float(wv[nt >> 1][(nt & 1) * 2 + 1]);
                uint32_t bh[2], bl[2];
                bh[0] = f2tf32(w0); bl[0] = f2tf32(w0 - tf2f(bh[0]));
                bh[1] = f2tf32(w1); bl[1] = f2tf32(w1 - tf2f(bh[1]));
                mma_tf32(d[0][nt], ah[0], bh);
                mma_tf32(d[1][nt], ah[1], bh);
                mma_tf32(d[0][nt], al[0], bh);
                mma_tf32(d[1][nt], al[1], bh);
                mma_tf32(d[0][nt], ah[0], bl);
                mma_tf32(d[1][nt], ah[1], bl);
            }
        }
    }

#pragma unroll
    for (int mt = 0; mt < 2; mt++) {
#pragma unroll
        for (int nt = 0; nt < 4; nt++) {
            int c = w * 32 + nt * 8 + 2 * tig;
            float b0 = __ldg(&bias[c]), b1 = __ldg(&bias[c + 1]);
            int ra = r0 + mt * 16 + g;
            int rb2 = ra + 8;
            float y0 = d[mt][nt][0] + b0, y1 = d[mt][nt][1] + b1;
            float y2 = d[mt][nt][2] + b0, y3 = d[mt][nt][3] + b1;
            if (khi) {
                uint32_t hi0 = bfpack(y1, y0);
                uint32_t lo0 = bfpack(y1 - bfhi_f(hi0), y0 - bflo_f(hi0));
                uint32_t hi1 = bfpack(y3, y2);
                uint32_t lo1 = bfpack(y3 - bfhi_f(hi1), y2 - bflo_f(hi1));
                khi[(size_t)ra  * 128 + (c >> 1)] = hi0;
                klo[(size_t)ra  * 128 + (c >> 1)] = lo0;
                khi[(size_t)rb2 * 128 + (c >> 1)] = hi1;
                klo[(size_t)rb2 * 128 + (c >> 1)] = lo1;
            } else {
                size_t o0 = (size_t)ra  * E_DIM + c;
                size_t o1 = (size_t)rb2 * E_DIM + c;
                if (add_residual) {
                    float2 x0 = *(const float2*)&X[o0];
                    float2 x1 = *(const float2*)&X[o1];
                    y0 += x0.x; y1 += x0.y; y2 += x1.x; y3 += x1.y;
                }
                *(float2*)&Y[o0] = make_float2(y0, y1);
                *(float2*)&Y[o1] = make_float2(y2, y3);
            }
        }
    }
}

__global__ __launch_bounds__(256, 2) void proj_qk_kernel(
    const float* __restrict__ Xq, const float* __restrict__ Wq, const float* __restrict__ bq,
    const float* __restrict__ Xk, const float* __restrict__ Wk, const float* __restrict__ bk,
    float* __restrict__ Yq, uint32_t* __restrict__ khi, uint32_t* __restrict__ klo)
{
    int r0 = blockIdx.x * 32;
    if (blockIdx.y == 0) proj_tc_body(Xq, Wq, bq, Yq, nullptr, nullptr, 0, r0);
    else                 proj_tc_body(Xk, Wk, bk, nullptr, khi, klo, 0, r0);
}

__global__ __launch_bounds__(256, 2) void proj_o_kernel(
    const float* __restrict__ X, const float* __restrict__ W,
    const float* __restrict__ bias, float* __restrict__ Y)
{
    proj_tc_body(X, W, bias, Y, nullptr, nullptr, 1, blockIdx.x * 32);
}

// ---------------------------------------------------------------------------
// attn_tc_kernel (R16 measured-best, unchanged): 512 threads, 2-stage
// cp.async, K fragments via ldmatrix.x4.
// ---------------------------------------------------------------------------
__global__ __launch_bounds__(512, 1) void attn_tc_kernel(
    const float* __restrict__ value,
    float* __restrict__ avgw,
    float* __restrict__ attn_out)
{
    extern __shared__ uint32_t smu[];
    float* Ps = (float*)(smu + PS_OFF);
    __shared__ float Lsh[16][32][4];

    const uint32_t sb = (uint32_t)__cvta_generic_to_shared(smu);

    const int tid  = threadIdx.x;
    const int wid  = tid >> 5;
    const int h    = wid & 7;
    const int sh   = wid >> 3;
    const int lane = tid & 31;
    const int g    = lane >> 2;
    const int tig  = lane & 3;
    const int r8   = lane & 7;
    const int quad = lane >> 3;
    const int t0   = blockIdx.x * 32;
    const int b    = blockIdx.y;
    const int hb   = h * DH;
    const int hw   = hb >> 1;

    // ---- Q fragments: bf16 2-split ----
    uint32_t qh[2][2][4], ql[2][2][4];
#pragma unroll
    for (int mt = 0; mt < 2; mt++) {
#pragma unroll
        for (int jc = 0; jc < 2; jc++) {
            int r = t0 + mt * 16 + g;
            int c = hb + jc * 16 + 2 * tig;
            float2 v0 = *(const float2*)&g_qproj[((size_t)r       * B_DIM + b) * E_DIM + c];
            float2 v1 = *(const float2*)&g_qproj[((size_t)(r + 8) * B_DIM + b) * E_DIM + c];
            float2 v2 = *(const float2*)&g_qproj[((size_t)r       * B_DIM + b) * E_DIM + c + 8];
            float2 v3 = *(const float2*)&g_qproj[((size_t)(r + 8) * B_DIM + b) * E_DIM + c + 8];
            qh[mt][jc][0] = bfpack(v0.y, v0.x);
            qh[mt][jc][1] = bfpack(v1.y, v1.x);
            qh[mt][jc][2] = bfpack(v2.y, v2.x);
            qh[mt][jc][3] = bfpack(v3.y, v3.x);
            ql[mt][jc][0] = bfpack(v0.y - bfhi_f(qh[mt][jc][0]), v0.x - bflo_f(qh[mt][jc][0]));
            ql[mt][jc][1] = bfpack(v1.y - bfhi_f(qh[mt][jc][1]), v1.x - bflo_f(qh[mt][jc][1]));
            ql[mt][jc][2] = bfpack(v2.y - bfhi_f(qh[mt][jc][2]), v2.x - bflo_f(qh[mt][jc][2]));
            ql[mt][jc][3] = bfpack(v3.y - bfhi_f(qh[mt][jc][3]), v3.x - bflo_f(qh[mt][jc][3]));
        }
    }

    // ========= pass 1: lsum via 1-term bf16 QK, 128-row tiles =========
    float lsum[4] = {0.f, 0.f, 0.f, 0.f};
    {
        const int NT1 = S_DIM / 128;          // 16

#pragma unroll
        for (int i = 0; i < 8; i++) {
            int idx = tid + i * 512;
            int row = idx >> 5, c = idx & 31;
            cpa16(sb + (uint32_t)(row * KWSTR + c * 4) * 4,
                  &g_khi[((size_t)row * B_DIM + b) * 128 + c * 4]);
        }
        CP_COMMIT();

        for (int t = 0; t < NT1; t++) {
            CP_WAIT0();
            __syncthreads();
            if (t + 1 < NT1) {
                int s0n = (t + 1) * 128;
                uint32_t dst = sb + (uint32_t)(((t + 1) & 1) * P1STAGE) * 4;
#pragma unroll
                for (int i = 0; i < 8; i++) {
                    int idx = tid + i * 512;
                    int row = idx >> 5, c = idx & 31;
                    cpa16(dst + (uint32_t)(row * KWSTR + c * 4) * 4,
                          &g_khi[((size_t)(s0n + row) * B_DIM + b) * 128 + c * 4]);
                }
            }
            CP_COMMIT();

            const uint32_t stage_w = (uint32_t)((t & 1) * P1STAGE);

#pragma unroll
            for (int sub = 0; sub < 2; sub++) {
                const int soW1 = sub * 64 + sh * 32;
                float d[2][4][4];
#pragma unroll
                for (int mt = 0; mt < 2; mt++)
#pragma unroll
                    for (int nt = 0; nt < 4; nt++)
#pragma unroll
                        for (int r = 0; r < 4; r++) d[mt][nt][r] = 0.f;

#pragma unroll
                for (int jc = 0; jc < 2; jc++) {
                    uint32_t bh[4][2];
#pragma unroll
                    for (int np = 0; np < 2; np++) {
                        int nt0 = np * 2;
                        int woff = (soW1 + (nt0 + (quad >> 1)) * 8 + r8) * KWSTR
                                 + hw + jc * 8 + (quad & 1) * 4;
                        uint32_t addr = sb + (stage_w + (uint32_t)woff) * 4;
                        asm volatile(
                            "ldmatrix.sync.aligned.m8n8.x4.shared.b16 {%0,%1,%2,%3}, [%4];"
                            : "=r"(bh[nt0][0]), "=r"(bh[nt0][1]),
                              "=r"(bh[nt0 + 1][0]), "=r"(bh[nt0 + 1][1])
                            : "r"(addr));
                    }
#pragma unroll
                    for (int nt = 0; nt < 4; nt++) {
                        mma_bf16(d[0][nt], qh[0][jc], bh[nt]);
                        mma_bf16(d[1][nt], qh[1][jc], bh[nt]);
                    }
                }
#pragma unroll
                for (int mt = 0; mt < 2; mt++)
#pragma unroll
                    for (int nt = 0; nt < 4; nt++)
#pragma unroll
                        for (int r = 0; r < 4; r++)
                            lsum[mt * 2 + (r >> 1)] += ex2f(d[mt][nt][r] * SCLOG2E);
            }
        }
    }
#pragma unroll
    for (int r = 0; r < 4; r++) {
        lsum[r] += __shfl_xor_sync(0xffffffffu, lsum[r], 1);
        lsum[r] += __shfl_xor_sync(0xffffffffu, lsum[r], 2);
    }
#pragma unroll
    for (int r = 0; r < 4; r++) Lsh[wid][lane][r] = lsum[r];
    __syncthreads();
    float inv[4];
#pragma unroll
    for (int r = 0; r < 4; r++) inv[r] = 1.0f / (lsum[r] + Lsh[wid ^ 8][lane][r]);

    // ================= pass 2 =================
    float o[2][4][4];
#pragma unroll
    for (int mt = 0; mt < 2; mt++)
#pragma unroll
        for (int nd = 0; nd < 4; nd++)
#pragma unroll
            for (int r = 0; r < 4; r++) o[mt][nd][r] = 0.f;

    const int soW = sh * 16;
    const int NT = S_DIM / 32;

    {
        uint32_t dkh = sb + (uint32_t)(KH_OFF) * 4;
        uint32_t dkl = sb + (uint32_t)(KL_OFF) * 4;
        uint32_t dv  = sb + (uint32_t)(V_OFF) * 4;
#pragma unroll
        for (int i = 0; i < 2; i++) {
            int idx = tid + i * 512;
            int row = idx >> 5, c = idx & 31;
            size_t gsrc = ((size_t)row * B_DIM + b) * 128 + c * 4;
            cpa16(dkh + (uint32_t)(row * KWSTR + c * 4) * 4, &g_khi[gsrc]);
            cpa16(dkl + (uint32_t)(row * KWSTR + c * 4) * 4, &g_klo[gsrc]);
        }
#pragma unroll
        for (int i = 0; i < 4; i++) {
            int idx = tid + i * 512;
            int row = idx >> 6, c = idx & 63;
            cpa16(dv + (uint32_t)(row * VSTR + c * 4) * 4,
                  &value[((size_t)row * B_DIM + b) * 256 + c * 4]);
        }
    }
    CP_COMMIT();

    for (int t = 0; t < NT; t++) {
        CP_WAIT0();
        __syncthreads();
        if (t + 1 < NT) {
            int nst = (t + 1) & 1;
            int s0n = (t + 1) * 32;
            uint32_t dkh = sb + (uint32_t)(KH_OFF + nst * 32 * KWSTR) * 4;
            uint32_t dkl = sb + (uint32_t)(KL_OFF + nst * 32 * KWSTR) * 4;
            uint32_t dv  = sb + (uint32_t)(V_OFF  + nst * 32 * VSTR) * 4;
#pragma unroll
            for (int i = 0; i < 2; i++) {
                int idx = tid + i * 512;
                int row = idx >> 5, c = idx & 31;
                size_t gsrc = ((size_t)(s0n + row) * B_DIM + b) * 128 + c * 4;
                cpa16(dkh + (uint32_t)(row * KWSTR + c * 4) * 4, &g_khi[gsrc]);
                cpa16(dkl + (uint32_t)(row * KWSTR + c * 4) * 4, &g_klo[gsrc]);
            }
#pragma unroll
            for (int i = 0; i < 4; i++) {
                int idx = tid + i * 512;
                int row = idx >> 6, c = idx & 63;
                cpa16(dv + (uint32_t)(row * VSTR + c * 4) * 4,
                      &value[((size_t)(s0n + row) * B_DIM + b) * 256 + c * 4]);
            }
        }
        CP_COMMIT();

        const int st = t & 1;
        const float* Vs = (const float*)(smu + V_OFF + st * 32 * VSTR);
        const uint32_t stage_w = (uint32_t)(KH_OFF + st * 32 * KWSTR);
        const int s0 = t * 32;

        float d[2][2][4];
#pragma unroll
        for (int mt = 0; mt < 2; mt++)
#pragma unroll
            for (int nt = 0; nt < 2; nt++)
#pragma unroll
                for (int r = 0; r < 4; r++) d[mt][nt][r] = 0.f;

#pragma unroll
        for (int jc = 0; jc < 2; jc++) {
            uint32_t bh[2][2], bl[2][2];
#pragma unroll
            for (int nt = 0; nt < 2; nt++) {
                int woff = (soW + nt * 8 + r8) * KWSTR + hw + jc * 8
                         + (quad & 1) * 4 + (quad >> 1) * (KL_OFF - KH_OFF);
                uint32_t addr = sb + (stage_w + (uint32_t)woff) * 4;
                asm volatile(
                    "ldmatrix.sync.aligned.m8n8.x4.shared.b16 {%0,%1,%2,%3}, [%4];"
                    : "=r"(bh[nt][0]), "=r"(bh[nt][1]), "=r"(bl[nt][0]), "=r"(bl[nt][1])
                    : "r"(addr));
            }
#pragma unroll
            for (int nt = 0; nt < 2; nt++) {
                mma_bf16(d[0][nt], qh[0][jc], bh[nt]);
                mma_bf16(d[1][nt], qh[1][jc], bh[nt]);
            }
#pragma unroll
            for (int nt = 0; nt < 2; nt++) {
                mma_bf16(d[0][nt], ql[0][jc], bh[nt]);
                mma_bf16(d[1][nt], ql[1][jc], bh[nt]);
            }
#pragma unroll
            for (int nt = 0; nt < 2; nt++) {
                mma_bf16(d[0][nt], qh[0][jc], bl[nt]);
                mma_bf16(d[1][nt], qh[1][jc], bl[nt]);
            }
        }

        // normalize, stage p into Ps
#pragma unroll
        for (int mt = 0; mt < 2; mt++) {
#pragma unroll
            for (int nt = 0; nt < 2; nt++) {
                float p0 = ex2f(d[mt][nt][0] * SCLOG2E) * inv[mt * 2 + 0];
                float p1 = ex2f(d[mt][nt][1] * SCLOG2E) * inv[mt * 2 + 0];
                float p2 = ex2f(d[mt][nt][2] * SCLOG2E) * inv[mt * 2 + 1];
                float p3 = ex2f(d[mt][nt][3] * SCLOG2E) * inv[mt * 2 + 1];
                int scol = soW + nt * 8 + 2 * tig;
                *(float2*)&Ps[h * PHEAD + (mt * 16 + g)     * PSTR + scol] = make_float2(p0, p1);
                *(float2*)&Ps[h * PHEAD + (mt * 16 + g + 8) * PSTR + scol] = make_float2(p2, p3);
            }
        }
        __syncwarp();

        // PV over this warp's 16 s-rows: 1xTF32
#pragma unroll
        for (int ks = 0; ks < 2; ks++) {
            uint32_t a[2][4];
            int sc = soW + ks * 8 + tig;
#pragma unroll
            for (int mt = 0; mt < 2; mt++) {
                int rb = mt * 16;
                a[mt][0] = f2tf32(Ps[h * PHEAD + (rb + g)     * PSTR + sc]);
                a[mt][1] = f2tf32(Ps[h * PHEAD + (rb + g + 8) * PSTR + sc]);
                a[mt][2] = f2tf32(Ps[h * PHEAD + (rb + g)     * PSTR + sc + 4]);
                a[mt][3] = f2tf32(Ps[h * PHEAD + (rb + g + 8) * PSTR + sc + 4]);
            }
#pragma unroll
            for (int nd = 0; nd < 4; nd++) {
                uint32_t bb[2];
                bb[0] = f2tf32(Vs[(soW + ks * 8 + tig)     * VSTR + hb + nd * 8 + g]);
                bb[1] = f2tf32(Vs[(soW + ks * 8 + tig + 4) * VSTR + hb + nd * 8 + g]);
                mma_tf32(o[0][nd], a[0], bb);
                mma_tf32(o[1][nd], a[1], bb);
            }
        }
        __syncthreads();

        // avg_weights tile [32 t x 32 s]
        {
            int row = tid >> 4;
            int sb2 = (tid & 15) * 2;
            float2 acc = make_float2(0.f, 0.f);
#pragma unroll
            for (int hh = 0; hh < 8; hh++) {
                float2 x = *(const float2*)&Ps[hh * PHEAD + row * PSTR + sb2];
                acc.x += x.x; acc.y += x.y;
            }
            acc.x *= 0.125f; acc.y *= 0.125f;
            size_t oo = (size_t)b * T_DIM * S_DIM + (size_t)(t0 + row) * S_DIM + s0 + sb2;
            *(float2*)&avgw[oo] = acc;
        }
    }

    // ---- merge s-half partial PV accumulators, write attn_out ----
    __syncthreads();
    float* Os = Ps;
    if (sh == 1) {
#pragma unroll
        for (int mt = 0; mt < 2; mt++)
#pragma unroll
            for (int nd = 0; nd < 4; nd++)
#pragma unroll
                for (int r = 0; r < 4; r++)
                    Os[(h * 32 + lane) * 33 + mt * 16 + nd * 4 + r] = o[mt][nd][r];
    }
    __syncthreads();
    if (sh == 0) {
#pragma unroll
        for (int mt = 0; mt < 2; mt++) {
#pragma unroll
            for (int nd = 0; nd < 4; nd++) {
#pragma unroll
                for (int r = 0; r < 4; r++)
                    o[mt][nd][r] += Os[(h * 32 + lane) * 33 + mt * 16 + nd * 4 + r];
                int col = hb + nd * 8 + 2 * tig;
                size_t b0 = ((size_t)(t0 + mt * 16 + g)     * B_DIM + b) * E_DIM + col;
                size_t b1 = ((size_t)(t0 + mt * 16 + g + 8) * B_DIM + b) * E_DIM + col;
                *(float2*)&attn_out[b0] = make_float2(o[mt][nd][0], o[mt][nd][1]);
                *(float2*)&attn_out[b1] = make_float2(o[mt][nd][2], o[mt][nd][3]);
            }
        }
    }
}

// ---------------------------------------------------------------------------
extern "C" void kernel_launch(void* const* d_in, const int* in_sizes, int n_in,
                              void* d_out, int out_size)
{
    (void)in_sizes; (void)n_in; (void)out_size;

    const float* query = (const float*)d_in[0];
    const float* key   = (const float*)d_in[1];
    const float* value = (const float*)d_in[2];
    const float* Wq    = (const float*)d_in[3];
    const float* bq    = (const float*)d_in[4];
    const float* Wk    = (const float*)d_in[5];
    const float* bk    = (const float*)d_in[6];
    const float* Wo    = (const float*)d_in[7];
    const float* bo    = (const float*)d_in[8];

    float* out  = (float*)d_out;
    float* avgw = out + (size_t)T_DIM * B_DIM * E_DIM;

    float *qp = nullptr, *ao = nullptr;
    uint32_t *khi = nullptr, *klo = nullptr;
    cudaGetSymbolAddress((void**)&qp,  g_qproj);
    cudaGetSymbolAddress((void**)&khi, g_khi);
    cudaGetSymbolAddress((void**)&klo, g_klo);
    cudaGetSymbolAddress((void**)&ao,  g_attnout);

    const int rows_blocks = (T_DIM * B_DIM) / 32;   // 128
    const int pj_smem = PJ_FLOATS * 4;              // 92160

    cudaFuncSetAttribute(proj_qk_kernel, cudaFuncAttributeMaxDynamicSharedMemorySize, pj_smem);
    cudaFuncSetAttribute(proj_o_kernel,  cudaFuncAttributeMaxDynamicSharedMemorySize, pj_smem);

    proj_qk_kernel<<<dim3(rows_blocks, 2), 256, pj_smem>>>(query, Wq, bq, key, Wk, bk, qp, khi, klo);

    const int smem_bytes = SMEM_WORDS * 4;  // 172032
    cudaFuncSetAttribute(attn_tc_kernel, cudaFuncAttributeMaxDynamicSharedMemorySize, smem_bytes);
    attn_tc_kernel<<<dim3(T_DIM / 32, B_DIM), 512, smem_bytes>>>(value, avgw, ao);

    proj_o_kernel<<<rows_blocks, 256, pj_smem>>>(ao, Wo, bo, out);
}